// round 11
// baseline (speedup 1.0000x reference)
#include <cuda_runtime.h>
#include <cuda_fp16.h>
#include <math.h>
#include <cstdint>

#define Bsz 16
#define Tt 64
#define NV 49
#define NP 50
#define Hd 512
#define BT (Bsz*Tt)              // 1024
#define M_ALL (BT*NP)            // 51200
#define M_T (Bsz*(Tt-1)*NP)      // 50400
#define NEGV (-1000000000.0f)

// -------- static device scratch (no allocations allowed) --------
__device__ float g_x[(size_t)M_ALL*Hd];
__device__ float g_sp[(size_t)M_ALL*Hd];
__device__ float g_z[(size_t)M_ALL*Hd];
__device__ float g_tmp[(size_t)M_ALL*Hd];
__device__ float g_cos[M_T];
__device__ __half g_xh[(size_t)M_ALL*Hd];
__device__ __half g_sph[(size_t)M_ALL*Hd];
__device__ __half g_zh[(size_t)M_ALL*Hd];
__device__ __half g_tmph[(size_t)M_ALL*Hd];
__device__ __half g_wh[8][512*512];   // fp16-rounded weights
__device__ __half g_sh[(size_t)BT*64*64];  // per-(b,t) S' matrices (fp16)

__device__ __forceinline__ size_t row_off(int r, int mode, int shift) {
    if (mode == 0) return (size_t)r * Hd;
    int b   = r / ((Tt-1)*NP);
    int rem = r - b*(Tt-1)*NP;
    int tt  = rem / NP;
    int i   = rem - tt*NP;
    return ((size_t)((b*Tt + tt + shift)*NP) + i) * Hd;
}

__device__ __forceinline__ uint32_t h2u(__half2 h) {
    return *reinterpret_cast<uint32_t*>(&h);
}
__device__ __forceinline__ void cpa16(uint32_t dst, const void* src) {
    asm volatile("cp.async.cg.shared.global [%0], [%1], 16;" :: "r"(dst), "l"(src));
}
__device__ __forceinline__ uint32_t smem_u32(const void* p) {
    uint32_t a;
    asm("{ .reg .u64 t; cvta.to.shared.u64 t, %1; cvt.u32.u64 %0, t; }" : "=r"(a) : "l"(p));
    return a;
}
__device__ __forceinline__ void ldm4(uint32_t addr, uint32_t* r) {
    asm volatile("ldmatrix.sync.aligned.m8n8.x4.shared.b16 {%0,%1,%2,%3}, [%4];"
                 : "=r"(r[0]), "=r"(r[1]), "=r"(r[2]), "=r"(r[3]) : "r"(addr));
}
__device__ __forceinline__ void ldm4t(uint32_t addr, uint32_t* r) {
    asm volatile("ldmatrix.sync.aligned.m8n8.x4.trans.shared.b16 {%0,%1,%2,%3}, [%4];"
                 : "=r"(r[0]), "=r"(r[1]), "=r"(r[2]), "=r"(r[3]) : "r"(addr));
}
#define MMA16816(acc, af, b0, b1) \
    asm volatile( \
        "mma.sync.aligned.m16n8k16.row.col.f32.f16.f16.f32 " \
        "{%0,%1,%2,%3}, {%4,%5,%6,%7}, {%8,%9}, {%0,%1,%2,%3};" \
        : "+f"((acc)[0]), "+f"((acc)[1]), "+f"((acc)[2]), "+f"((acc)[3]) \
        : "r"((af)[0]), "r"((af)[1]), "r"((af)[2]), "r"((af)[3]), \
          "r"(b0), "r"(b1))

// -------- round all 8 f32 weight matrices to fp16 (RN), one launch --------
struct WPtrs { const float* p[8]; };
__global__ void round_h_k(WPtrs w, __half* __restrict__ out) {
    size_t i = (size_t)blockIdx.x * blockDim.x + threadIdx.x;
    int m = (int)(i >> 18);
    int e = (int)(i & 0x3FFFF);
    out[i] = __float2half_rn(w.p[m][e]);
}

// -------- concat(visual, audio) -> dense [BT*NP, H] + half copy --------
__global__ void concat_kernel(const float* __restrict__ vis,
                              const float* __restrict__ aud,
                              float* __restrict__ out,
                              __half* __restrict__ outh) {
    size_t idx = (size_t)blockIdx.x * blockDim.x + threadIdx.x;
    size_t total = (size_t)M_ALL * (Hd/4);
    if (idx >= total) return;
    int h4 = (int)(idx & 127);
    size_t row = idx >> 7;
    int i = (int)(row % NP);
    size_t bt = row / NP;
    float4 v;
    if (i < NV) v = ((const float4*)vis)[(bt*NV + i)*(Hd/4) + h4];
    else        v = ((const float4*)aud)[bt*(Hd/4) + h4];
    ((float4*)out)[idx] = v;
    __half2 h0 = __floats2half2_rn(v.x, v.y);
    __half2 h1 = __floats2half2_rn(v.z, v.w);
    __half2* oh = (__half2*)(outh + idx*4);
    oh[0] = h0; oh[1] = h1;
}

// ============ fp16 mma.sync GEMM, K-chunk 64, 3-stage cp.async ============
#define SROWH 72
#define ASTG_B (128*SROWH*2)
#define NSTAGE 3
#define GH_SMEM (2*NSTAGE*ASTG_B)

__global__ void __launch_bounds__(256, 2) gemm_fp16(
    const __half* __restrict__ A, int amode, int ashift,
    const float* __restrict__ scale, int smode,
    const __half* __restrict__ W,
    const float* __restrict__ bias, int relu_flag,
    const float* __restrict__ add1, int a1mode, int a1shift,
    const float* __restrict__ add2,
    float* __restrict__ C, __half* __restrict__ Ch,
    int cmode, int cshift, int M)
{
    extern __shared__ char smraw[];
    const uint32_t sm0 = smem_u32(smraw);
    const int tid  = threadIdx.x;
    const int wid  = tid >> 5;
    const int lane = tid & 31;
    const int tig  = lane & 3;
    const int wm   = wid & 1;
    const int wn   = wid >> 1;
    const int nb   = blockIdx.x;
    const int row0 = blockIdx.y * 128;
    const int g    = lane >> 2;

    const int ar = tid >> 1, ah = tid & 1;
    int gra = row0 + ar; if (gra >= M) gra = M - 1;
    const __half* aptr = A + row_off(gra, amode, ashift) + ah*32;
    const __half* bptr = W + (size_t)(nb*128 + ar)*Hd + ah*32;
    const uint32_t sa_addr = sm0 + (uint32_t)(ar*SROWH + ah*32)*2;
    const uint32_t sb_addr = sm0 + (uint32_t)(NSTAGE*128*SROWH + ar*SROWH + ah*32)*2;

    auto CPAB = [&](int st, int k0) {
        uint32_t so = (uint32_t)st * ASTG_B;
        #pragma unroll
        for (int j = 0; j < 4; j++)
            cpa16(sa_addr + so + j*16, aptr + k0 + j*8);
        #pragma unroll
        for (int j = 0; j < 4; j++)
            cpa16(sb_addr + so + j*16, bptr + k0 + j*8);
        asm volatile("cp.async.commit_group;" ::: "memory");
    };

    uint32_t la[4], lb[2];
    #pragma unroll
    for (int mt = 0; mt < 4; mt++)
        la[mt] = sm0 + (uint32_t)((wm*64 + mt*16 + (lane & 15))*SROWH + (lane >> 4)*8)*2;
    #pragma unroll
    for (int ntp = 0; ntp < 2; ntp++)
        lb[ntp] = sm0 + (uint32_t)(NSTAGE*128*SROWH)*2
                + (uint32_t)((wn*32 + ntp*16 + (lane & 15))*SROWH + (lane >> 4)*8)*2;

    float acc[4][4][4];
    #pragma unroll
    for (int a = 0; a < 4; a++)
        #pragma unroll
        for (int b = 0; b < 4; b++)
            #pragma unroll
            for (int c = 0; c < 4; c++) acc[a][b][c] = 0.f;

    CPAB(0, 0);
    CPAB(1, 64);

    const int NTILES = Hd/64;
    for (int kt = 0; kt < NTILES; kt++) {
        const int st = kt % NSTAGE;
        const uint32_t soff = (uint32_t)st * ASTG_B;
        if (kt + 1 < NTILES) asm volatile("cp.async.wait_group 1;" ::: "memory");
        else                 asm volatile("cp.async.wait_group 0;" ::: "memory");
        __syncthreads();
        #pragma unroll
        for (int ks = 0; ks < 4; ks++) {
            const uint32_t kb = soff + ks*32;
            uint32_t bf0[4], bf1[4];
            ldm4(lb[0] + kb, bf0);
            ldm4(lb[1] + kb, bf1);
            #pragma unroll
            for (int mt = 0; mt < 4; mt++) {
                uint32_t af[4];
                ldm4(la[mt] + kb, af);
                #pragma unroll
                for (int nt = 0; nt < 4; nt++) {
                    const uint32_t* bp = (nt & 2) ? bf1 : bf0;
                    const int sel = nt & 1;
                    MMA16816(acc[mt][nt], af, bp[sel], bp[sel+2]);
                }
            }
        }
        if (kt + 2 < NTILES) CPAB((kt + 2) % NSTAGE, (kt + 2) * 64);
    }

    #pragma unroll
    for (int mt = 0; mt < 4; mt++) {
        #pragma unroll
        for (int hf = 0; hf < 2; hf++) {
            int r = row0 + wm*64 + mt*16 + g + hf*8;
            if (r >= M) continue;
            size_t co  = row_off(r, cmode, cshift);
            size_t a1o = add1 ? row_off(r, a1mode, a1shift) : 0;
            float sc = 1.f;
            if (smode) { float v = scale[r]; sc = (smode == 1) ? v : (1.f - v); }
            #pragma unroll
            for (int nt = 0; nt < 4; nt++) {
                int n = nb*128 + wn*32 + nt*8 + tig*2;
                float vx = acc[mt][nt][hf*2+0];
                float vy = acc[mt][nt][hf*2+1];
                if (smode) { vx *= sc; vy *= sc; }
                if (bias)  { vx += bias[n]; vy += bias[n+1]; }
                if (relu_flag) { vx = fmaxf(vx, 0.f); vy = fmaxf(vy, 0.f); }
                if (add1)  { vx += add1[a1o + n]; vy += add1[a1o + n + 1]; }
                if (add2)  { vx += add2[(size_t)r*Hd + n]; vy += add2[(size_t)r*Hd + n + 1]; }
                *(float2*)(C + co + n) = make_float2(vx, vy);
                if (Ch) *(__half2*)(Ch + co + n) = __floats2half2_rn(vx, vy);
            }
        }
    }
}

// ============ attn kernel 1: Gram(fp16 mma) + scores + softmax -> S' ============
#define K1_XH   0
#define K1_G    66560                 // 64*520*2
#define K1_S    (K1_G + 64*66*4)      // 83456
#define K1_QN   (K1_S + 50*52*4)      // 94272
#define K1_KN0  (K1_QN + 200)
#define K1_KN1  (K1_KN0 + 196)
#define K1_SAV  (K1_KN1 + 196)
#define K1_A49  (K1_SAV + 200)
#define K1_RED  (K1_A49 + 200)
#define K1_SMEM (K1_RED + 144)
#define GSTR 66

__global__ __launch_bounds__(512, 2) void attn_score_kernel(
    const float* __restrict__ X, const float* __restrict__ edge,
    float* __restrict__ attn_out, __half* __restrict__ Sout)
{
    extern __shared__ char smraw[];
    float*  G  = (float*)(smraw + K1_G);
    float*  S  = (float*)(smraw + K1_S);
    float*  qn = (float*)(smraw + K1_QN);
    float*  kn0= (float*)(smraw + K1_KN0);
    float*  kn1= (float*)(smraw + K1_KN1);
    float*  sAv= (float*)(smraw + K1_SAV);
    float*  a49= (float*)(smraw + K1_A49);
    float*  red= (float*)(smraw + K1_RED);

    const int bt   = blockIdx.x;
    const int tid  = threadIdx.x;
    const int lane = tid & 31, warp = tid >> 5;

    // load rows 0-49 = x, 50-52 = edge, 53-63 = 0, as fp16, row stride 520
    {
        const float4* xg = (const float4*)(X + (size_t)bt*NP*Hd);
        const float4* eg = (const float4*)edge;
        for (int u = tid; u < 64*128; u += 512) {
            int row = u >> 7, c4 = u & 127;
            float4 v;
            if (row < NP)      v = xg[row*128 + c4];
            else if (row < 53) v = eg[(row - NP)*128 + c4];
            else               v = make_float4(0.f, 0.f, 0.f, 0.f);
            uint2 pk;
            pk.x = h2u(__floats2half2_rn(v.x, v.y));
            pk.y = h2u(__floats2half2_rn(v.z, v.w));
            *(uint2*)(smraw + K1_XH + (row*520 + c4*4)*2) = pk;
        }
    }
    __syncthreads();

    // Gram G[64x64] = Xh @ Xh^T via fp16 mma; 16 warps x (16x16) tiles
    {
        const uint32_t xb = smem_u32(smraw) + K1_XH;
        const int wm = warp & 3, wn = warp >> 2;
        uint32_t la = xb + (uint32_t)((wm*16 + (lane & 15))*520 + (lane >> 4)*8)*2;
        uint32_t lb = xb + (uint32_t)((wn*16 + (lane & 15))*520 + (lane >> 4)*8)*2;
        float gacc[2][4];
        #pragma unroll
        for (int a = 0; a < 2; a++)
            #pragma unroll
            for (int b = 0; b < 4; b++) gacc[a][b] = 0.f;
        #pragma unroll 8
        for (int kk = 0; kk < 32; kk++) {
            const uint32_t kb = kk*32;      // 16 halves
            uint32_t af[4], bf[4];
            ldm4(la + kb, af);
            ldm4(lb + kb, bf);
            MMA16816(gacc[0], af, bf[0], bf[2]);
            MMA16816(gacc[1], af, bf[1], bf[3]);
        }
        #pragma unroll
        for (int nt = 0; nt < 2; nt++) {
            int gr = wm*16 + (lane >> 2);
            int gc = wn*16 + nt*8 + (lane & 3)*2;
            *(float2*)&G[gr*GSTR + gc]     = make_float2(gacc[nt][0], gacc[nt][1]);
            *(float2*)&G[(gr+8)*GSTR + gc] = make_float2(gacc[nt][2], gacc[nt][3]);
        }
    }
    __syncthreads();

    if (tid < 50) qn[tid] = fmaxf(sqrtf(G[tid*GSTR+tid]), 1e-12f);
    if (tid >= 64 && tid < 64+49) {
        int j = tid - 64;
        kn0[j] = fmaxf(sqrtf(G[j*GSTR+j] + 2.f*G[j*GSTR+50] + G[50*GSTR+50]), 1e-12f);
    }
    if (tid >= 128 && tid < 128+49) {
        int j = tid - 128;
        kn1[j] = fmaxf(sqrtf(G[j*GSTR+j] + 2.f*G[j*GSTR+51] + G[51*GSTR+51]), 1e-12f);
    }
    if (tid == 192)
        red[33] = fmaxf(sqrtf(G[49*GSTR+49] + 2.f*G[49*GSTR+52] + G[52*GSTR+52]), 1e-12f);
    __syncthreads();
    const float kn2 = red[33];

    for (int p = tid; p < 2500; p += 512) {
        int i = p / 50, j = p - (p/50)*50;
        float v;
        if (i == j)       v = NEGV;
        else if (j == 49) v = (G[i*GSTR+49] + G[i*GSTR+52]) / (qn[i]*kn2);
        else if (i == 49) v = (G[49*GSTR+j] + G[49*GSTR+51]) / (qn[49]*kn1[j]);
        else {
            int qr = i/7, qc = i - (i/7)*7, kr = j/7, kc = j - (j/7)*7;
            int r0 = (qr-1 > 0) ? qr-1 : 0;
            int c0 = qc-1; c0 = (c0 < 0) ? 0 : ((c0 > 4) ? 4 : c0);
            bool ok = (kr >= r0 && kr <= r0+2 && kc >= c0 && kc <= c0+2);
            v = ok ? (G[i*GSTR+j] + G[i*GSTR+50]) / (qn[i]*kn0[j]) : NEGV;
        }
        S[i*52+j] = v;
    }
    __syncthreads();

    for (int i = warp; i < 50; i += 16) {
        float v0 = S[i*52 + lane];
        int j1 = lane + 32;
        float v1 = (j1 < 50) ? S[i*52 + j1] : -3.4e38f;
        float m = fmaxf(v0, v1);
        #pragma unroll
        for (int o = 16; o; o >>= 1) m = fmaxf(m, __shfl_xor_sync(0xffffffffu, m, o));
        float e0 = expf(v0 - m);
        float e1 = (j1 < 50) ? expf(v1 - m) : 0.f;
        float s = e0 + e1;
        #pragma unroll
        for (int o = 16; o; o >>= 1) s += __shfl_xor_sync(0xffffffffu, s, o);
        float e49 = __shfl_sync(0xffffffffu, e1, 17);
        float inv = 1.f / s;
        float p0 = e0 * inv, p1 = e1 * inv;
        S[i*52 + lane] = p0;
        if (j1 < 50) S[i*52 + j1] = p1;
        if (lane == 0) { sAv[i] = (s - e49)*inv; a49[i] = e49*inv; }
        if (attn_out) {
            attn_out[((size_t)bt*50 + i)*50 + lane] = p0;
            if (j1 < 50) attn_out[((size_t)bt*50 + i)*50 + j1] = p1;
        }
    }
    __syncthreads();

    // pack S' fp16 [64x64]: cols 50/51/52 carry edge coefficients
    __half* sout = Sout + (size_t)bt*4096;
    for (int p = tid; p < 4096; p += 512) {
        int i = p >> 6, j = p & 63;
        float v = 0.f;
        if (i < 50) {
            if (j < 50)       v = S[i*52 + j];
            else if (j == 50) v = (i < 49)  ? sAv[i]  : 0.f;
            else if (j == 51) v = (i == 49) ? sAv[49] : 0.f;
            else if (j == 52) v = a49[i];
        }
        sout[p] = __float2half_rn(v);
    }
}

// ============ attn kernel 2: agg = S' @ X (fp16 mma) + residual + LN ============
#define K2_SH   0                         // 64*72 halves = 9216B
#define K2_XH   9216                      // 64*520 halves = 66560B
#define K2_PART (K2_XH + 66560)           // 64*8 floats = 2048B
#define K2_MU   (K2_PART + 2048)          // 64 floats
#define K2_RS   (K2_MU + 256)             // 64 floats
#define K2_GB   (K2_RS + 256)             // 1024 floats
#define K2_SMEM (K2_GB + 4096)

__global__ __launch_bounds__(512, 2) void agg_ln_kernel(
    const float* __restrict__ X, const float* __restrict__ edge,
    const __half* __restrict__ Sin,
    const float* __restrict__ lng, const float* __restrict__ lnb,
    float* __restrict__ spatial, __half* __restrict__ spatial_h)
{
    extern __shared__ char smraw[];
    float* part = (float*)(smraw + K2_PART);
    float* muA  = (float*)(smraw + K2_MU);
    float* rsA  = (float*)(smraw + K2_RS);
    float* gb   = (float*)(smraw + K2_GB);

    const int bt   = blockIdx.x;
    const int tid  = threadIdx.x;
    const int lane = tid & 31, warp = tid >> 5;
    const int g = lane >> 2, tig = lane & 3;

    // load X (+edges) as fp16 rows 0-63, stride 520
    {
        const float4* xg = (const float4*)(X + (size_t)bt*NP*Hd);
        const float4* eg = (const float4*)edge;
        for (int u = tid; u < 64*128; u += 512) {
            int row = u >> 7, c4 = u & 127;
            float4 v;
            if (row < NP)      v = xg[row*128 + c4];
            else if (row < 53) v = eg[(row - NP)*128 + c4];
            else               v = make_float4(0.f, 0.f, 0.f, 0.f);
            uint2 pk;
            pk.x = h2u(__floats2half2_rn(v.x, v.y));
            pk.y = h2u(__floats2half2_rn(v.z, v.w));
            *(uint2*)(smraw + K2_XH + (row*520 + c4*4)*2) = pk;
        }
    }
    // load S' into smem (stride 72)
    {
        const uint4* sg = (const uint4*)(Sin + (size_t)bt*4096);
        uint4 v = sg[tid];
        int row = tid >> 3, col8 = (tid & 7)*8;
        *(uint4*)(smraw + K2_SH + (row*72 + col8)*2) = v;
    }
    gb[tid]       = lng[tid];
    gb[512 + tid] = lnb[tid];
    __syncthreads();

    // mma: rows = wm*16 tile, cols = wn*128
    const int wm = warp & 3, wn = warp >> 2;
    const uint32_t sm0 = smem_u32(smraw);
    uint32_t la = sm0 + K2_SH + (uint32_t)((wm*16 + (lane & 15))*72 + (lane >> 4)*8)*2;
    uint32_t lbrow = sm0 + K2_XH
                   + (uint32_t)(((lane & 7) + 8*((lane >> 3) & 1))*520)*2
                   + (uint32_t)((lane >> 4)*8)*2;

    float acc[16][4];
    #pragma unroll
    for (int a = 0; a < 16; a++)
        #pragma unroll
        for (int b = 0; b < 4; b++) acc[a][b] = 0.f;

    #pragma unroll
    for (int kk = 0; kk < 4; kk++) {
        uint32_t af[4];
        ldm4(la + kk*32, af);
        #pragma unroll
        for (int nb2 = 0; nb2 < 8; nb2++) {
            uint32_t bf[4];
            ldm4t(lbrow + (uint32_t)(kk*16*520)*2 + (uint32_t)((wn*128 + nb2*16))*2, bf);
            MMA16816(acc[nb2*2],   af, bf[0], bf[1]);
            MMA16816(acc[nb2*2+1], af, bf[2], bf[3]);
        }
    }

    // residual add (fp32) + per-row stats
    const int r0g = wm*16 + g, r1g = r0g + 8;
    const float* x0 = X + ((size_t)bt*NP + r0g)*Hd;
    const float* x1 = X + ((size_t)bt*NP + r1g)*Hd;
    float s1a = 0.f, s2a = 0.f, s1b = 0.f, s2b = 0.f;
    #pragma unroll
    for (int nt = 0; nt < 16; nt++) {
        int c = wn*128 + (nt >> 1)*16 + (nt & 1)*8 + tig*2;
        if (r0g < NP) {
            float2 rx = *(const float2*)(x0 + c);
            acc[nt][0] += rx.x; acc[nt][1] += rx.y;
            s1a += acc[nt][0] + acc[nt][1];
            s2a += acc[nt][0]*acc[nt][0] + acc[nt][1]*acc[nt][1];
        }
        if (r1g < NP) {
            float2 rx = *(const float2*)(x1 + c);
            acc[nt][2] += rx.x; acc[nt][3] += rx.y;
            s1b += acc[nt][2] + acc[nt][3];
            s2b += acc[nt][2]*acc[nt][2] + acc[nt][3]*acc[nt][3];
        }
    }
    #pragma unroll
    for (int o = 1; o <= 2; o <<= 1) {
        s1a += __shfl_xor_sync(0xffffffffu, s1a, o);
        s2a += __shfl_xor_sync(0xffffffffu, s2a, o);
        s1b += __shfl_xor_sync(0xffffffffu, s1b, o);
        s2b += __shfl_xor_sync(0xffffffffu, s2b, o);
    }
    if (tig == 0) {
        part[r0g*8 + wn]     = s1a;
        part[r0g*8 + 4 + wn] = s2a;
        part[r1g*8 + wn]     = s1b;
        part[r1g*8 + 4 + wn] = s2b;
    }
    __syncthreads();
    if (tid < 64) {
        float s1 = part[tid*8+0] + part[tid*8+1] + part[tid*8+2] + part[tid*8+3];
        float s2 = part[tid*8+4] + part[tid*8+5] + part[tid*8+6] + part[tid*8+7];
        float mu = s1 * (1.f/512.f);
        muA[tid] = mu;
        rsA[tid] = rsqrtf(s2*(1.f/512.f) - mu*mu + 1e-5f);
    }
    __syncthreads();

    // normalize + relu + dual write
    #pragma unroll
    for (int hr = 0; hr < 2; hr++) {
        int r = hr ? r1g : r0g;
        if (r >= NP) continue;
        float mu = muA[r], rs = rsA[r];
        float*  dst  = spatial   + ((size_t)bt*NP + r)*Hd;
        __half* dsth = spatial_h + ((size_t)bt*NP + r)*Hd;
        #pragma unroll
        for (int nt = 0; nt < 16; nt++) {
            int c = wn*128 + (nt >> 1)*16 + (nt & 1)*8 + tig*2;
            float vx = acc[nt][hr*2+0], vy = acc[nt][hr*2+1];
            float ox = fmaxf(0.f, (vx - mu)*rs*gb[c]   + gb[512 + c]);
            float oy = fmaxf(0.f, (vy - mu)*rs*gb[c+1] + gb[512 + c + 1]);
            *(float2*)(dst + c) = make_float2(ox, oy);
            *(__half2*)(dsth + c) = __floats2half2_rn(ox, oy);
        }
    }
}

// -------- cosine between spatial[t] and spatial[t-1] --------
__global__ void cos_kernel(const float* __restrict__ sp,
                           float* __restrict__ c1, float* __restrict__ c2) {
    int gw = (int)((blockIdx.x*(size_t)blockDim.x + threadIdx.x) >> 5);
    int lane = threadIdx.x & 31;
    if (gw >= M_T) return;
    int b   = gw / ((Tt-1)*NP);
    int rem = gw - b*(Tt-1)*NP;
    int tt  = rem / NP;
    int i   = rem - tt*NP;
    const float4* pa = (const float4*)(sp + (((size_t)(b*Tt + tt + 1))*NP + i)*Hd);
    const float4* pb = (const float4*)(sp + (((size_t)(b*Tt + tt))*NP + i)*Hd);
    float d = 0.f, na = 0.f, nb2 = 0.f;
    for (int u = lane; u < 128; u += 32) {
        float4 a = pa[u], c = pb[u];
        d   += a.x*c.x + a.y*c.y + a.z*c.z + a.w*c.w;
        na  += a.x*a.x + a.y*a.y + a.z*a.z + a.w*a.w;
        nb2 += c.x*c.x + c.y*c.y + c.z*c.z + c.w*c.w;
    }
    #pragma unroll
    for (int o = 16; o; o >>= 1) {
        d   += __shfl_xor_sync(0xffffffffu, d, o);
        na  += __shfl_xor_sync(0xffffffffu, na, o);
        nb2 += __shfl_xor_sync(0xffffffffu, nb2, o);
    }
    if (lane == 0) {
        float v = d / (fmaxf(sqrtf(na), 1e-8f) * fmaxf(sqrtf(nb2), 1e-8f));
        c1[gw] = v;
        if (c2) c2[gw] = v;
    }
}

// -------- copy t=0 rows of spatial into z --------
__global__ void copy_t0(const float* __restrict__ sp, float* __restrict__ z) {
    int u = blockIdx.x*blockDim.x + threadIdx.x;
    if (u >= Bsz*NP*(Hd/4)) return;
    int h4 = u & 127;
    int rem = u >> 7;
    int i = rem % NP;
    int b = rem / NP;
    size_t off = ((size_t)(b*Tt)*NP + i)*(Hd/4) + h4;
    ((float4*)z)[off] = ((const float4*)sp)[off];
}

// -------- LayerNorm rows of 512, block per row, dual fp32+fp16 out --------
__global__ __launch_bounds__(512) void ln512(const float* __restrict__ X,
                                             const float* __restrict__ g,
                                             const float* __restrict__ b,
                                             float* __restrict__ Y,
                                             __half* __restrict__ Yh) {
    __shared__ float red[34];
    size_t base = (size_t)blockIdx.x * Hd;
    int tid = threadIdx.x, lane = tid & 31, warp = tid >> 5;
    float v = X[base + tid];
    float s1 = v, s2 = v*v;
    #pragma unroll
    for (int o = 16; o; o >>= 1) {
        s1 += __shfl_xor_sync(0xffffffffu, s1, o);
        s2 += __shfl_xor_sync(0xffffffffu, s2, o);
    }
    if (!lane) { red[warp] = s1; red[16+warp] = s2; }
    __syncthreads();
    if (warp == 0) {
        float a = (lane < 16) ? red[lane]    : 0.f;
        float c = (lane < 16) ? red[16+lane] : 0.f;
        #pragma unroll
        for (int o = 8; o; o >>= 1) {
            a += __shfl_xor_sync(0xffffffffu, a, o);
            c += __shfl_xor_sync(0xffffffffu, c, o);
        }
        if (!lane) {
            float m = a * (1.f/512.f);
            red[32] = m;
            red[33] = rsqrtf(c*(1.f/512.f) - m*m + 1e-5f);
        }
    }
    __syncthreads();
    float o = (v - red[32])*red[33]*g[tid] + b[tid];
    Y[base + tid]  = o;
    Yh[base + tid] = __float2half_rn(o);
}

extern "C" void kernel_launch(void* const* d_in, const int* in_sizes, int n_in,
                              void* d_out, int out_size) {
    (void)in_sizes; (void)n_in; (void)out_size;
    const float* vis   = (const float*)d_in[0];
    const float* aud   = (const float*)d_in[1];
    const float* in_W  = (const float*)d_in[2];
    const float* in_b  = (const float*)d_in[3];
    const float* out_W = (const float*)d_in[4];
    const float* out_b = (const float*)d_in[5];

    float* out      = (float*)d_out;
    float* attn_out = out + (size_t)M_ALL*Hd;
    float* cos_out  = attn_out + (size_t)BT*NP*NP;

    float *gx, *gsp, *gz, *gtmp, *gcos;
    __half *gxh, *gsph, *gzh, *gtmph, *gwh, *gsh;
    cudaGetSymbolAddress((void**)&gx,    g_x);
    cudaGetSymbolAddress((void**)&gsp,   g_sp);
    cudaGetSymbolAddress((void**)&gz,    g_z);
    cudaGetSymbolAddress((void**)&gtmp,  g_tmp);
    cudaGetSymbolAddress((void**)&gcos,  g_cos);
    cudaGetSymbolAddress((void**)&gxh,   g_xh);
    cudaGetSymbolAddress((void**)&gsph,  g_sph);
    cudaGetSymbolAddress((void**)&gzh,   g_zh);
    cudaGetSymbolAddress((void**)&gtmph, g_tmph);
    cudaGetSymbolAddress((void**)&gwh,   g_wh);
    cudaGetSymbolAddress((void**)&gsh,   g_sh);

    cudaFuncSetAttribute(attn_score_kernel,
                         cudaFuncAttributeMaxDynamicSharedMemorySize, K1_SMEM);
    cudaFuncSetAttribute(agg_ln_kernel,
                         cudaFuncAttributeMaxDynamicSharedMemorySize, K2_SMEM);
    cudaFuncSetAttribute(gemm_fp16,
                         cudaFuncAttributeMaxDynamicSharedMemorySize, GH_SMEM);

    WPtrs wp;
    wp.p[0] = in_W;  wp.p[1] = out_W;
    wp.p[2] = (const float*)d_in[9];  wp.p[3] = (const float*)d_in[11];
    wp.p[4] = (const float*)d_in[13]; wp.p[5] = (const float*)d_in[17];
    wp.p[6] = (const float*)d_in[19]; wp.p[7] = (const float*)d_in[21];
    round_h_k<<<8192, 256>>>(wp, gwh);
    const __half* W_in  = gwh;
    const __half* W_out = gwh + (size_t)1*512*512;
    const __half* W_l[2][3] = { { gwh+(size_t)2*512*512, gwh+(size_t)3*512*512, gwh+(size_t)4*512*512 },
                                { gwh+(size_t)5*512*512, gwh+(size_t)6*512*512, gwh+(size_t)7*512*512 } };

    concat_kernel<<<(M_ALL*128 + 255)/256, 256>>>(vis, aud, gz, gzh);
    dim3 gAll(4, (M_ALL + 127)/128);
    gemm_fp16<<<gAll, 256, GH_SMEM>>>(gzh, 0, 0, nullptr, 0, W_in, in_b, 0,
                                      nullptr, 0, 0, nullptr, gx, nullptr, 0, 0, M_ALL);

    for (int L = 0; L < 2; L++) {
        const float* edge = (const float*)d_in[6 + L*8];
        const float* lng  = (const float*)d_in[7 + L*8];
        const float* lnb  = (const float*)d_in[8 + L*8];
        const float* bc   = (const float*)d_in[10 + L*8];
        const float* bs   = (const float*)d_in[12 + L*8];

        attn_score_kernel<<<BT, 512, K1_SMEM>>>(
            gx, edge, (L == 1) ? attn_out : nullptr, gsh);
        agg_ln_kernel<<<BT, 512, K2_SMEM>>>(
            gx, edge, gsh, lng, lnb, gsp, gsph);

        cos_kernel<<<(M_T*32 + 255)/256, 256>>>(gsp, gcos, (L == 1) ? cos_out : nullptr);

        dim3 gT(4, (M_T + 127)/128);
        gemm_fp16<<<gT, 256, GH_SMEM>>>(gsph, 1, 0, gcos, 1, W_l[L][0], bc, 1,
                                        nullptr, 0, 0, nullptr, gtmp, nullptr, 0, 0, M_T);
        gemm_fp16<<<gT, 256, GH_SMEM>>>(gsph, 1, 1, gcos, 2, W_l[L][1], bs, 1,
                                        gsp, 1, 1, gtmp, gz, nullptr, 1, 1, M_T);
        copy_t0<<<(Bsz*NP*128 + 255)/256, 256>>>(gsp, gz);

        ln512<<<M_ALL, 512>>>(gz, lng, lnb, gtmp, gtmph);
        gemm_fp16<<<gAll, 256, GH_SMEM>>>(gtmph, 0, 0, nullptr, 0, W_l[L][2], nullptr, 1,
                                          gx, 0, 0, nullptr, gx, (L == 1) ? gxh : nullptr,
                                          0, 0, M_ALL);
    }

    gemm_fp16<<<gAll, 256, GH_SMEM>>>(gxh, 0, 0, nullptr, 0, W_out, out_b, 0,
                                      nullptr, 0, 0, nullptr, out, nullptr, 0, 0, M_ALL);
}

// round 12
// speedup vs baseline: 1.5045x; 1.5045x over previous
#include <cuda_runtime.h>
#include <cuda_fp16.h>
#include <math.h>
#include <cstdint>

#define Bsz 16
#define Tt 64
#define NV 49
#define NP 50
#define Hd 512
#define BT (Bsz*Tt)              // 1024
#define M_ALL (BT*NP)            // 51200
#define M_T (Bsz*(Tt-1)*NP)      // 50400
#define NEGV (-1000000000.0f)

// -------- static device scratch (no allocations allowed) --------
__device__ float g_x[(size_t)M_ALL*Hd];
__device__ float g_sp[(size_t)M_ALL*Hd];
__device__ float g_z[(size_t)M_ALL*Hd];
__device__ float g_tmp[(size_t)M_ALL*Hd];
__device__ float g_cos[M_T];
__device__ __half g_xh[(size_t)M_ALL*Hd];
__device__ __half g_sph[(size_t)M_ALL*Hd];
__device__ __half g_zh[(size_t)M_ALL*Hd];
__device__ __half g_tmph[(size_t)M_ALL*Hd];
__device__ __half g_wh[8][512*512];   // fp16-rounded weights
__device__ __half g_sh[(size_t)BT*64*64];  // per-(b,t) S' matrices (fp16)

__device__ __forceinline__ size_t row_off(int r, int mode, int shift) {
    if (mode == 0) return (size_t)r * Hd;
    int b   = r / ((Tt-1)*NP);
    int rem = r - b*(Tt-1)*NP;
    int tt  = rem / NP;
    int i   = rem - tt*NP;
    return ((size_t)((b*Tt + tt + shift)*NP) + i) * Hd;
}

__device__ __forceinline__ uint32_t h2u(__half2 h) {
    return *reinterpret_cast<uint32_t*>(&h);
}
__device__ __forceinline__ void cpa16(uint32_t dst, const void* src) {
    asm volatile("cp.async.cg.shared.global [%0], [%1], 16;" :: "r"(dst), "l"(src));
}
__device__ __forceinline__ uint32_t smem_u32(const void* p) {
    uint32_t a;
    asm("{ .reg .u64 t; cvta.to.shared.u64 t, %1; cvt.u32.u64 %0, t; }" : "=r"(a) : "l"(p));
    return a;
}
__device__ __forceinline__ void ldm4(uint32_t addr, uint32_t* r) {
    asm volatile("ldmatrix.sync.aligned.m8n8.x4.shared.b16 {%0,%1,%2,%3}, [%4];"
                 : "=r"(r[0]), "=r"(r[1]), "=r"(r[2]), "=r"(r[3]) : "r"(addr));
}
__device__ __forceinline__ void ldm4t(uint32_t addr, uint32_t* r) {
    asm volatile("ldmatrix.sync.aligned.m8n8.x4.trans.shared.b16 {%0,%1,%2,%3}, [%4];"
                 : "=r"(r[0]), "=r"(r[1]), "=r"(r[2]), "=r"(r[3]) : "r"(addr));
}
#define MMA16816(acc, af, b0, b1) \
    asm volatile( \
        "mma.sync.aligned.m16n8k16.row.col.f32.f16.f16.f32 " \
        "{%0,%1,%2,%3}, {%4,%5,%6,%7}, {%8,%9}, {%0,%1,%2,%3};" \
        : "+f"((acc)[0]), "+f"((acc)[1]), "+f"((acc)[2]), "+f"((acc)[3]) \
        : "r"((af)[0]), "r"((af)[1]), "r"((af)[2]), "r"((af)[3]), \
          "r"(b0), "r"(b1))

// -------- round all 8 f32 weight matrices to fp16 (RN), one launch --------
struct WPtrs { const float* p[8]; };
__global__ void round_h_k(WPtrs w, __half* __restrict__ out) {
    size_t i = (size_t)blockIdx.x * blockDim.x + threadIdx.x;
    int m = (int)(i >> 18);
    int e = (int)(i & 0x3FFFF);
    out[i] = __float2half_rn(w.p[m][e]);
}

// -------- concat(visual, audio) -> dense [BT*NP, H] + half copy --------
__global__ void concat_kernel(const float* __restrict__ vis,
                              const float* __restrict__ aud,
                              float* __restrict__ out,
                              __half* __restrict__ outh) {
    size_t idx = (size_t)blockIdx.x * blockDim.x + threadIdx.x;
    size_t total = (size_t)M_ALL * (Hd/4);
    if (idx >= total) return;
    int h4 = (int)(idx & 127);
    size_t row = idx >> 7;
    int i = (int)(row % NP);
    size_t bt = row / NP;
    float4 v;
    if (i < NV) v = ((const float4*)vis)[(bt*NV + i)*(Hd/4) + h4];
    else        v = ((const float4*)aud)[bt*(Hd/4) + h4];
    ((float4*)out)[idx] = v;
    __half2 h0 = __floats2half2_rn(v.x, v.y);
    __half2 h1 = __floats2half2_rn(v.z, v.w);
    __half2* oh = (__half2*)(outh + idx*4);
    oh[0] = h0; oh[1] = h1;
}

// ============ fp16 mma.sync GEMM, K-chunk 64, 3-stage cp.async ============
#define SROWH 72
#define ASTG_B (128*SROWH*2)
#define NSTAGE 3
#define GH_SMEM (2*NSTAGE*ASTG_B)

__global__ void __launch_bounds__(256, 2) gemm_fp16(
    const __half* __restrict__ A, int amode, int ashift,
    const float* __restrict__ scale, int smode,
    const __half* __restrict__ W,
    const float* __restrict__ bias, int relu_flag,
    const float* __restrict__ add1, int a1mode, int a1shift,
    const float* __restrict__ add2,
    float* __restrict__ C, __half* __restrict__ Ch,
    int cmode, int cshift, int M)
{
    extern __shared__ char smraw[];
    const uint32_t sm0 = smem_u32(smraw);
    const int tid  = threadIdx.x;
    const int wid  = tid >> 5;
    const int lane = tid & 31;
    const int tig  = lane & 3;
    const int wm   = wid & 1;
    const int wn   = wid >> 1;
    const int nb   = blockIdx.x;
    const int row0 = blockIdx.y * 128;
    const int g    = lane >> 2;

    const int ar = tid >> 1, ah = tid & 1;
    int gra = row0 + ar; if (gra >= M) gra = M - 1;
    const __half* aptr = A + row_off(gra, amode, ashift) + ah*32;
    const __half* bptr = W + (size_t)(nb*128 + ar)*Hd + ah*32;
    const uint32_t sa_addr = sm0 + (uint32_t)(ar*SROWH + ah*32)*2;
    const uint32_t sb_addr = sm0 + (uint32_t)(NSTAGE*128*SROWH + ar*SROWH + ah*32)*2;

    auto CPAB = [&](int st, int k0) {
        uint32_t so = (uint32_t)st * ASTG_B;
        #pragma unroll
        for (int j = 0; j < 4; j++)
            cpa16(sa_addr + so + j*16, aptr + k0 + j*8);
        #pragma unroll
        for (int j = 0; j < 4; j++)
            cpa16(sb_addr + so + j*16, bptr + k0 + j*8);
        asm volatile("cp.async.commit_group;" ::: "memory");
    };

    uint32_t la[4], lb[2];
    #pragma unroll
    for (int mt = 0; mt < 4; mt++)
        la[mt] = sm0 + (uint32_t)((wm*64 + mt*16 + (lane & 15))*SROWH + (lane >> 4)*8)*2;
    #pragma unroll
    for (int ntp = 0; ntp < 2; ntp++)
        lb[ntp] = sm0 + (uint32_t)(NSTAGE*128*SROWH)*2
                + (uint32_t)((wn*32 + ntp*16 + (lane & 15))*SROWH + (lane >> 4)*8)*2;

    float acc[4][4][4];
    #pragma unroll
    for (int a = 0; a < 4; a++)
        #pragma unroll
        for (int b = 0; b < 4; b++)
            #pragma unroll
            for (int c = 0; c < 4; c++) acc[a][b][c] = 0.f;

    CPAB(0, 0);
    CPAB(1, 64);

    const int NTILES = Hd/64;
    for (int kt = 0; kt < NTILES; kt++) {
        const int st = kt % NSTAGE;
        const uint32_t soff = (uint32_t)st * ASTG_B;
        if (kt + 1 < NTILES) asm volatile("cp.async.wait_group 1;" ::: "memory");
        else                 asm volatile("cp.async.wait_group 0;" ::: "memory");
        __syncthreads();
        #pragma unroll
        for (int ks = 0; ks < 4; ks++) {
            const uint32_t kb = soff + ks*32;
            uint32_t bf0[4], bf1[4];
            ldm4(lb[0] + kb, bf0);
            ldm4(lb[1] + kb, bf1);
            #pragma unroll
            for (int mt = 0; mt < 4; mt++) {
                uint32_t af[4];
                ldm4(la[mt] + kb, af);
                #pragma unroll
                for (int nt = 0; nt < 4; nt++) {
                    const uint32_t* bp = (nt & 2) ? bf1 : bf0;
                    const int sel = nt & 1;
                    MMA16816(acc[mt][nt], af, bp[sel], bp[sel+2]);
                }
            }
        }
        if (kt + 2 < NTILES) CPAB((kt + 2) % NSTAGE, (kt + 2) * 64);
    }

    #pragma unroll
    for (int mt = 0; mt < 4; mt++) {
        #pragma unroll
        for (int hf = 0; hf < 2; hf++) {
            int r = row0 + wm*64 + mt*16 + g + hf*8;
            if (r >= M) continue;
            size_t co  = row_off(r, cmode, cshift);
            size_t a1o = add1 ? row_off(r, a1mode, a1shift) : 0;
            float sc = 1.f;
            if (smode) { float v = scale[r]; sc = (smode == 1) ? v : (1.f - v); }
            #pragma unroll
            for (int nt = 0; nt < 4; nt++) {
                int n = nb*128 + wn*32 + nt*8 + tig*2;
                float vx = acc[mt][nt][hf*2+0];
                float vy = acc[mt][nt][hf*2+1];
                if (smode) { vx *= sc; vy *= sc; }
                if (bias)  { vx += bias[n]; vy += bias[n+1]; }
                if (relu_flag) { vx = fmaxf(vx, 0.f); vy = fmaxf(vy, 0.f); }
                if (add1)  { vx += add1[a1o + n]; vy += add1[a1o + n + 1]; }
                if (add2)  { vx += add2[(size_t)r*Hd + n]; vy += add2[(size_t)r*Hd + n + 1]; }
                *(float2*)(C + co + n) = make_float2(vx, vy);
                if (Ch) *(__half2*)(Ch + co + n) = __floats2half2_rn(vx, vy);
            }
        }
    }
}

// ============ attn kernel 1: Gram(fp16 mma) + scores + softmax -> S' ============
#define K1_XH   0
#define K1_G    66560                 // 64*520*2
#define K1_S    (K1_G + 64*66*4)      // 83456
#define K1_QN   (K1_S + 50*52*4)      // 94272
#define K1_KN0  (K1_QN + 200)
#define K1_KN1  (K1_KN0 + 196)
#define K1_SAV  (K1_KN1 + 196)
#define K1_A49  (K1_SAV + 200)
#define K1_RED  (K1_A49 + 200)
#define K1_SMEM (K1_RED + 144)
#define GSTR 66

__global__ __launch_bounds__(512, 2) void attn_score_kernel(
    const float* __restrict__ X, const float* __restrict__ edge,
    float* __restrict__ attn_out, __half* __restrict__ Sout)
{
    extern __shared__ char smraw[];
    float*  G  = (float*)(smraw + K1_G);
    float*  S  = (float*)(smraw + K1_S);
    float*  qn = (float*)(smraw + K1_QN);
    float*  kn0= (float*)(smraw + K1_KN0);
    float*  kn1= (float*)(smraw + K1_KN1);
    float*  sAv= (float*)(smraw + K1_SAV);
    float*  a49= (float*)(smraw + K1_A49);
    float*  red= (float*)(smraw + K1_RED);

    const int bt   = blockIdx.x;
    const int tid  = threadIdx.x;
    const int lane = tid & 31, warp = tid >> 5;

    // load rows 0-49 = x, 50-52 = edge, 53-63 = 0, as fp16, row stride 520
    {
        const float4* xg = (const float4*)(X + (size_t)bt*NP*Hd);
        const float4* eg = (const float4*)edge;
        for (int u = tid; u < 64*128; u += 512) {
            int row = u >> 7, c4 = u & 127;
            float4 v;
            if (row < NP)      v = xg[row*128 + c4];
            else if (row < 53) v = eg[(row - NP)*128 + c4];
            else               v = make_float4(0.f, 0.f, 0.f, 0.f);
            uint2 pk;
            pk.x = h2u(__floats2half2_rn(v.x, v.y));
            pk.y = h2u(__floats2half2_rn(v.z, v.w));
            *(uint2*)(smraw + K1_XH + (row*520 + c4*4)*2) = pk;
        }
    }
    __syncthreads();

    // Gram G[64x64] = Xh @ Xh^T via fp16 mma; 16 warps x (16x16) tiles
    {
        const uint32_t xb = smem_u32(smraw) + K1_XH;
        const int wm = warp & 3, wn = warp >> 2;
        uint32_t la = xb + (uint32_t)((wm*16 + (lane & 15))*520 + (lane >> 4)*8)*2;
        uint32_t lb = xb + (uint32_t)((wn*16 + (lane & 15))*520 + (lane >> 4)*8)*2;
        float gacc[2][4];
        #pragma unroll
        for (int a = 0; a < 2; a++)
            #pragma unroll
            for (int b = 0; b < 4; b++) gacc[a][b] = 0.f;
        #pragma unroll 8
        for (int kk = 0; kk < 32; kk++) {
            const uint32_t kb = kk*32;      // 16 halves
            uint32_t af[4], bf[4];
            ldm4(la + kb, af);
            ldm4(lb + kb, bf);
            MMA16816(gacc[0], af, bf[0], bf[2]);
            MMA16816(gacc[1], af, bf[1], bf[3]);
        }
        #pragma unroll
        for (int nt = 0; nt < 2; nt++) {
            int gr = wm*16 + (lane >> 2);
            int gc = wn*16 + nt*8 + (lane & 3)*2;
            *(float2*)&G[gr*GSTR + gc]     = make_float2(gacc[nt][0], gacc[nt][1]);
            *(float2*)&G[(gr+8)*GSTR + gc] = make_float2(gacc[nt][2], gacc[nt][3]);
        }
    }
    __syncthreads();

    if (tid < 50) qn[tid] = fmaxf(sqrtf(G[tid*GSTR+tid]), 1e-12f);
    if (tid >= 64 && tid < 64+49) {
        int j = tid - 64;
        kn0[j] = fmaxf(sqrtf(G[j*GSTR+j] + 2.f*G[j*GSTR+50] + G[50*GSTR+50]), 1e-12f);
    }
    if (tid >= 128 && tid < 128+49) {
        int j = tid - 128;
        kn1[j] = fmaxf(sqrtf(G[j*GSTR+j] + 2.f*G[j*GSTR+51] + G[51*GSTR+51]), 1e-12f);
    }
    if (tid == 192)
        red[33] = fmaxf(sqrtf(G[49*GSTR+49] + 2.f*G[49*GSTR+52] + G[52*GSTR+52]), 1e-12f);
    __syncthreads();
    const float kn2 = red[33];

    for (int p = tid; p < 2500; p += 512) {
        int i = p / 50, j = p - (p/50)*50;
        float v;
        if (i == j)       v = NEGV;
        else if (j == 49) v = (G[i*GSTR+49] + G[i*GSTR+52]) / (qn[i]*kn2);
        else if (i == 49) v = (G[49*GSTR+j] + G[49*GSTR+51]) / (qn[49]*kn1[j]);
        else {
            int qr = i/7, qc = i - (i/7)*7, kr = j/7, kc = j - (j/7)*7;
            int r0 = (qr-1 > 0) ? qr-1 : 0;
            int c0 = qc-1; c0 = (c0 < 0) ? 0 : ((c0 > 4) ? 4 : c0);
            bool ok = (kr >= r0 && kr <= r0+2 && kc >= c0 && kc <= c0+2);
            v = ok ? (G[i*GSTR+j] + G[i*GSTR+50]) / (qn[i]*kn0[j]) : NEGV;
        }
        S[i*52+j] = v;
    }
    __syncthreads();

    for (int i = warp; i < 50; i += 16) {
        float v0 = S[i*52 + lane];
        int j1 = lane + 32;
        float v1 = (j1 < 50) ? S[i*52 + j1] : -3.4e38f;
        float m = fmaxf(v0, v1);
        #pragma unroll
        for (int o = 16; o; o >>= 1) m = fmaxf(m, __shfl_xor_sync(0xffffffffu, m, o));
        float e0 = expf(v0 - m);
        float e1 = (j1 < 50) ? expf(v1 - m) : 0.f;
        float s = e0 + e1;
        #pragma unroll
        for (int o = 16; o; o >>= 1) s += __shfl_xor_sync(0xffffffffu, s, o);
        float e49 = __shfl_sync(0xffffffffu, e1, 17);
        float inv = 1.f / s;
        float p0 = e0 * inv, p1 = e1 * inv;
        S[i*52 + lane] = p0;
        if (j1 < 50) S[i*52 + j1] = p1;
        if (lane == 0) { sAv[i] = (s - e49)*inv; a49[i] = e49*inv; }
        if (attn_out) {
            attn_out[((size_t)bt*50 + i)*50 + lane] = p0;
            if (j1 < 50) attn_out[((size_t)bt*50 + i)*50 + j1] = p1;
        }
    }
    __syncthreads();

    // pack S' fp16 [64x64]: cols 50/51/52 carry edge coefficients
    __half* sout = Sout + (size_t)bt*4096;
    for (int p = tid; p < 4096; p += 512) {
        int i = p >> 6, j = p & 63;
        float v = 0.f;
        if (i < 50) {
            if (j < 50)       v = S[i*52 + j];
            else if (j == 50) v = (i < 49)  ? sAv[i]  : 0.f;
            else if (j == 51) v = (i == 49) ? sAv[49] : 0.f;
            else if (j == 52) v = a49[i];
        }
        sout[p] = __float2half_rn(v);
    }
}

// ============ attn kernel 2: agg = S' @ X (fp16 mma) + residual + LN ============
#define K2_SH   0                         // 64*72 halves = 9216B
#define K2_XH   9216                      // 64*520 halves = 66560B
#define K2_PART (K2_XH + 66560)           // 64*8 floats = 2048B
#define K2_MU   (K2_PART + 2048)          // 64 floats
#define K2_RS   (K2_MU + 256)             // 64 floats
#define K2_GB   (K2_RS + 256)             // 1024 floats
#define K2_SMEM (K2_GB + 4096)

__global__ __launch_bounds__(512, 1) void agg_ln_kernel(
    const float* __restrict__ X, const float* __restrict__ edge,
    const __half* __restrict__ Sin,
    const float* __restrict__ lng, const float* __restrict__ lnb,
    float* __restrict__ spatial, __half* __restrict__ spatial_h)
{
    extern __shared__ char smraw[];
    float* part = (float*)(smraw + K2_PART);
    float* muA  = (float*)(smraw + K2_MU);
    float* rsA  = (float*)(smraw + K2_RS);
    float* gb   = (float*)(smraw + K2_GB);

    const int bt   = blockIdx.x;
    const int tid  = threadIdx.x;
    const int lane = tid & 31, warp = tid >> 5;
    const int g = lane >> 2, tig = lane & 3;

    // load X (+edges) as fp16 rows 0-63, stride 520
    {
        const float4* xg = (const float4*)(X + (size_t)bt*NP*Hd);
        const float4* eg = (const float4*)edge;
        for (int u = tid; u < 64*128; u += 512) {
            int row = u >> 7, c4 = u & 127;
            float4 v;
            if (row < NP)      v = xg[row*128 + c4];
            else if (row < 53) v = eg[(row - NP)*128 + c4];
            else               v = make_float4(0.f, 0.f, 0.f, 0.f);
            uint2 pk;
            pk.x = h2u(__floats2half2_rn(v.x, v.y));
            pk.y = h2u(__floats2half2_rn(v.z, v.w));
            *(uint2*)(smraw + K2_XH + (row*520 + c4*4)*2) = pk;
        }
    }
    // load S' into smem (stride 72)
    {
        const uint4* sg = (const uint4*)(Sin + (size_t)bt*4096);
        uint4 v = sg[tid];
        int row = tid >> 3, col8 = (tid & 7)*8;
        *(uint4*)(smraw + K2_SH + (row*72 + col8)*2) = v;
    }
    gb[tid]       = lng[tid];
    gb[512 + tid] = lnb[tid];
    __syncthreads();

    // mma: rows = wm*16 tile, cols = wn*128
    const int wm = warp & 3, wn = warp >> 2;
    const uint32_t sm0 = smem_u32(smraw);
    uint32_t la = sm0 + K2_SH + (uint32_t)((wm*16 + (lane & 15))*72 + (lane >> 4)*8)*2;
    uint32_t lbrow = sm0 + K2_XH
                   + (uint32_t)(((lane & 7) + 8*((lane >> 3) & 1))*520)*2
                   + (uint32_t)((lane >> 4)*8)*2;

    float acc[16][4];
    #pragma unroll
    for (int a = 0; a < 16; a++)
        #pragma unroll
        for (int b = 0; b < 4; b++) acc[a][b] = 0.f;

    #pragma unroll
    for (int kk = 0; kk < 4; kk++) {
        uint32_t af[4];
        ldm4(la + kk*32, af);
        #pragma unroll
        for (int nb2 = 0; nb2 < 8; nb2++) {
            uint32_t bf[4];
            ldm4t(lbrow + (uint32_t)(kk*16*520)*2 + (uint32_t)((wn*128 + nb2*16))*2, bf);
            MMA16816(acc[nb2*2],   af, bf[0], bf[1]);
            MMA16816(acc[nb2*2+1], af, bf[2], bf[3]);
        }
    }

    // residual add (fp32) + per-row stats
    const int r0g = wm*16 + g, r1g = r0g + 8;
    const float* x0 = X + ((size_t)bt*NP + r0g)*Hd;
    const float* x1 = X + ((size_t)bt*NP + r1g)*Hd;
    float s1a = 0.f, s2a = 0.f, s1b = 0.f, s2b = 0.f;
    #pragma unroll
    for (int nt = 0; nt < 16; nt++) {
        int c = wn*128 + (nt >> 1)*16 + (nt & 1)*8 + tig*2;
        if (r0g < NP) {
            float2 rx = *(const float2*)(x0 + c);
            acc[nt][0] += rx.x; acc[nt][1] += rx.y;
            s1a += acc[nt][0] + acc[nt][1];
            s2a += acc[nt][0]*acc[nt][0] + acc[nt][1]*acc[nt][1];
        }
        if (r1g < NP) {
            float2 rx = *(const float2*)(x1 + c);
            acc[nt][2] += rx.x; acc[nt][3] += rx.y;
            s1b += acc[nt][2] + acc[nt][3];
            s2b += acc[nt][2]*acc[nt][2] + acc[nt][3]*acc[nt][3];
        }
    }
    #pragma unroll
    for (int o = 1; o <= 2; o <<= 1) {
        s1a += __shfl_xor_sync(0xffffffffu, s1a, o);
        s2a += __shfl_xor_sync(0xffffffffu, s2a, o);
        s1b += __shfl_xor_sync(0xffffffffu, s1b, o);
        s2b += __shfl_xor_sync(0xffffffffu, s2b, o);
    }
    if (tig == 0) {
        part[r0g*8 + wn]     = s1a;
        part[r0g*8 + 4 + wn] = s2a;
        part[r1g*8 + wn]     = s1b;
        part[r1g*8 + 4 + wn] = s2b;
    }
    __syncthreads();
    if (tid < 64) {
        float s1 = part[tid*8+0] + part[tid*8+1] + part[tid*8+2] + part[tid*8+3];
        float s2 = part[tid*8+4] + part[tid*8+5] + part[tid*8+6] + part[tid*8+7];
        float mu = s1 * (1.f/512.f);
        muA[tid] = mu;
        rsA[tid] = rsqrtf(s2*(1.f/512.f) - mu*mu + 1e-5f);
    }
    __syncthreads();

    // normalize + relu + dual write
    #pragma unroll
    for (int hr = 0; hr < 2; hr++) {
        int r = hr ? r1g : r0g;
        if (r >= NP) continue;
        float mu = muA[r], rs = rsA[r];
        float*  dst  = spatial   + ((size_t)bt*NP + r)*Hd;
        __half* dsth = spatial_h + ((size_t)bt*NP + r)*Hd;
        #pragma unroll
        for (int nt = 0; nt < 16; nt++) {
            int c = wn*128 + (nt >> 1)*16 + (nt & 1)*8 + tig*2;
            float vx = acc[nt][hr*2+0], vy = acc[nt][hr*2+1];
            float ox = fmaxf(0.f, (vx - mu)*rs*gb[c]   + gb[512 + c]);
            float oy = fmaxf(0.f, (vy - mu)*rs*gb[c+1] + gb[512 + c + 1]);
            *(float2*)(dst + c) = make_float2(ox, oy);
            *(__half2*)(dsth + c) = __floats2half2_rn(ox, oy);
        }
    }
}

// -------- cosine between spatial[t] and spatial[t-1] --------
__global__ void cos_kernel(const float* __restrict__ sp,
                           float* __restrict__ c1, float* __restrict__ c2) {
    int gw = (int)((blockIdx.x*(size_t)blockDim.x + threadIdx.x) >> 5);
    int lane = threadIdx.x & 31;
    if (gw >= M_T) return;
    int b   = gw / ((Tt-1)*NP);
    int rem = gw - b*(Tt-1)*NP;
    int tt  = rem / NP;
    int i   = rem - tt*NP;
    const float4* pa = (const float4*)(sp + (((size_t)(b*Tt + tt + 1))*NP + i)*Hd);
    const float4* pb = (const float4*)(sp + (((size_t)(b*Tt + tt))*NP + i)*Hd);
    float d = 0.f, na = 0.f, nb2 = 0.f;
    for (int u = lane; u < 128; u += 32) {
        float4 a = pa[u], c = pb[u];
        d   += a.x*c.x + a.y*c.y + a.z*c.z + a.w*c.w;
        na  += a.x*a.x + a.y*a.y + a.z*a.z + a.w*a.w;
        nb2 += c.x*c.x + c.y*c.y + c.z*c.z + c.w*c.w;
    }
    #pragma unroll
    for (int o = 16; o; o >>= 1) {
        d   += __shfl_xor_sync(0xffffffffu, d, o);
        na  += __shfl_xor_sync(0xffffffffu, na, o);
        nb2 += __shfl_xor_sync(0xffffffffu, nb2, o);
    }
    if (lane == 0) {
        float v = d / (fmaxf(sqrtf(na), 1e-8f) * fmaxf(sqrtf(nb2), 1e-8f));
        c1[gw] = v;
        if (c2) c2[gw] = v;
    }
}

// -------- copy t=0 rows of spatial into z --------
__global__ void copy_t0(const float* __restrict__ sp, float* __restrict__ z) {
    int u = blockIdx.x*blockDim.x + threadIdx.x;
    if (u >= Bsz*NP*(Hd/4)) return;
    int h4 = u & 127;
    int rem = u >> 7;
    int i = rem % NP;
    int b = rem / NP;
    size_t off = ((size_t)(b*Tt)*NP + i)*(Hd/4) + h4;
    ((float4*)z)[off] = ((const float4*)sp)[off];
}

// -------- LayerNorm rows of 512, block per row, dual fp32+fp16 out --------
__global__ __launch_bounds__(512) void ln512(const float* __restrict__ X,
                                             const float* __restrict__ g,
                                             const float* __restrict__ b,
                                             float* __restrict__ Y,
                                             __half* __restrict__ Yh) {
    __shared__ float red[34];
    size_t base = (size_t)blockIdx.x * Hd;
    int tid = threadIdx.x, lane = tid & 31, warp = tid >> 5;
    float v = X[base + tid];
    float s1 = v, s2 = v*v;
    #pragma unroll
    for (int o = 16; o; o >>= 1) {
        s1 += __shfl_xor_sync(0xffffffffu, s1, o);
        s2 += __shfl_xor_sync(0xffffffffu, s2, o);
    }
    if (!lane) { red[warp] = s1; red[16+warp] = s2; }
    __syncthreads();
    if (warp == 0) {
        float a = (lane < 16) ? red[lane]    : 0.f;
        float c = (lane < 16) ? red[16+lane] : 0.f;
        #pragma unroll
        for (int o = 8; o; o >>= 1) {
            a += __shfl_xor_sync(0xffffffffu, a, o);
            c += __shfl_xor_sync(0xffffffffu, c, o);
        }
        if (!lane) {
            float m = a * (1.f/512.f);
            red[32] = m;
            red[33] = rsqrtf(c*(1.f/512.f) - m*m + 1e-5f);
        }
    }
    __syncthreads();
    float o = (v - red[32])*red[33]*g[tid] + b[tid];
    Y[base + tid]  = o;
    Yh[base + tid] = __float2half_rn(o);
}

extern "C" void kernel_launch(void* const* d_in, const int* in_sizes, int n_in,
                              void* d_out, int out_size) {
    (void)in_sizes; (void)n_in; (void)out_size;
    const float* vis   = (const float*)d_in[0];
    const float* aud   = (const float*)d_in[1];
    const float* in_W  = (const float*)d_in[2];
    const float* in_b  = (const float*)d_in[3];
    const float* out_W = (const float*)d_in[4];
    const float* out_b = (const float*)d_in[5];

    float* out      = (float*)d_out;
    float* attn_out = out + (size_t)M_ALL*Hd;
    float* cos_out  = attn_out + (size_t)BT*NP*NP;

    float *gx, *gsp, *gz, *gtmp, *gcos;
    __half *gxh, *gsph, *gzh, *gtmph, *gwh, *gsh;
    cudaGetSymbolAddress((void**)&gx,    g_x);
    cudaGetSymbolAddress((void**)&gsp,   g_sp);
    cudaGetSymbolAddress((void**)&gz,    g_z);
    cudaGetSymbolAddress((void**)&gtmp,  g_tmp);
    cudaGetSymbolAddress((void**)&gcos,  g_cos);
    cudaGetSymbolAddress((void**)&gxh,   g_xh);
    cudaGetSymbolAddress((void**)&gsph,  g_sph);
    cudaGetSymbolAddress((void**)&gzh,   g_zh);
    cudaGetSymbolAddress((void**)&gtmph, g_tmph);
    cudaGetSymbolAddress((void**)&gwh,   g_wh);
    cudaGetSymbolAddress((void**)&gsh,   g_sh);

    cudaFuncSetAttribute(attn_score_kernel,
                         cudaFuncAttributeMaxDynamicSharedMemorySize, K1_SMEM);
    cudaFuncSetAttribute(agg_ln_kernel,
                         cudaFuncAttributeMaxDynamicSharedMemorySize, K2_SMEM);
    cudaFuncSetAttribute(gemm_fp16,
                         cudaFuncAttributeMaxDynamicSharedMemorySize, GH_SMEM);

    WPtrs wp;
    wp.p[0] = in_W;  wp.p[1] = out_W;
    wp.p[2] = (const float*)d_in[9];  wp.p[3] = (const float*)d_in[11];
    wp.p[4] = (const float*)d_in[13]; wp.p[5] = (const float*)d_in[17];
    wp.p[6] = (const float*)d_in[19]; wp.p[7] = (const float*)d_in[21];
    round_h_k<<<8192, 256>>>(wp, gwh);
    const __half* W_in  = gwh;
    const __half* W_out = gwh + (size_t)1*512*512;
    const __half* W_l[2][3] = { { gwh+(size_t)2*512*512, gwh+(size_t)3*512*512, gwh+(size_t)4*512*512 },
                                { gwh+(size_t)5*512*512, gwh+(size_t)6*512*512, gwh+(size_t)7*512*512 } };

    concat_kernel<<<(M_ALL*128 + 255)/256, 256>>>(vis, aud, gz, gzh);
    dim3 gAll(4, (M_ALL + 127)/128);
    gemm_fp16<<<gAll, 256, GH_SMEM>>>(gzh, 0, 0, nullptr, 0, W_in, in_b, 0,
                                      nullptr, 0, 0, nullptr, gx, nullptr, 0, 0, M_ALL);

    for (int L = 0; L < 2; L++) {
        const float* edge = (const float*)d_in[6 + L*8];
        const float* lng  = (const float*)d_in[7 + L*8];
        const float* lnb  = (const float*)d_in[8 + L*8];
        const float* bc   = (const float*)d_in[10 + L*8];
        const float* bs   = (const float*)d_in[12 + L*8];

        attn_score_kernel<<<BT, 512, K1_SMEM>>>(
            gx, edge, (L == 1) ? attn_out : nullptr, gsh);
        agg_ln_kernel<<<BT, 512, K2_SMEM>>>(
            gx, edge, gsh, lng, lnb, gsp, gsph);

        cos_kernel<<<(M_T*32 + 255)/256, 256>>>(gsp, gcos, (L == 1) ? cos_out : nullptr);

        dim3 gT(4, (M_T + 127)/128);
        gemm_fp16<<<gT, 256, GH_SMEM>>>(gsph, 1, 0, gcos, 1, W_l[L][0], bc, 1,
                                        nullptr, 0, 0, nullptr, gtmp, nullptr, 0, 0, M_T);
        gemm_fp16<<<gT, 256, GH_SMEM>>>(gsph, 1, 1, gcos, 2, W_l[L][1], bs, 1,
                                        gsp, 1, 1, gtmp, gz, nullptr, 1, 1, M_T);
        copy_t0<<<(Bsz*NP*128 + 255)/256, 256>>>(gsp, gz);

        ln512<<<M_ALL, 512>>>(gz, lng, lnb, gtmp, gtmph);
        gemm_fp16<<<gAll, 256, GH_SMEM>>>(gtmph, 0, 0, nullptr, 0, W_l[L][2], nullptr, 1,
                                          gx, 0, 0, nullptr, gx, (L == 1) ? gxh : nullptr,
                                          0, 0, M_ALL);
    }

    gemm_fp16<<<gAll, 256, GH_SMEM>>>(gxh, 0, 0, nullptr, 0, W_out, out_b, 0,
                                      nullptr, 0, 0, nullptr, out, nullptr, 0, 0, M_ALL);
}

// round 13
// speedup vs baseline: 1.5250x; 1.0137x over previous
#include <cuda_runtime.h>
#include <cuda_fp16.h>
#include <math.h>
#include <cstdint>

#define Bsz 16
#define Tt 64
#define NV 49
#define NP 50
#define Hd 512
#define BT (Bsz*Tt)              // 1024
#define M_ALL (BT*NP)            // 51200
#define M_T (Bsz*(Tt-1)*NP)      // 50400
#define NEGV (-1000000000.0f)

// -------- static device scratch (no allocations allowed) --------
__device__ float g_x[(size_t)M_ALL*Hd];
__device__ float g_sp[(size_t)M_ALL*Hd];
__device__ float g_z[(size_t)M_ALL*Hd];
__device__ float g_tmp[(size_t)M_ALL*Hd];
__device__ float g_cos[M_T];
__device__ __half g_xh[(size_t)M_ALL*Hd];
__device__ __half g_sph[(size_t)M_ALL*Hd];
__device__ __half g_zh[(size_t)M_ALL*Hd];
__device__ __half g_tmph[(size_t)M_ALL*Hd];
__device__ __half g_wh[8][512*512];   // fp16-rounded weights
__device__ __half g_sh[(size_t)BT*64*64];  // per-(b,t) S' matrices (fp16)

__device__ __forceinline__ size_t row_off(int r, int mode, int shift) {
    if (mode == 0) return (size_t)r * Hd;
    int b   = r / ((Tt-1)*NP);
    int rem = r - b*(Tt-1)*NP;
    int tt  = rem / NP;
    int i   = rem - tt*NP;
    return ((size_t)((b*Tt + tt + shift)*NP) + i) * Hd;
}

__device__ __forceinline__ uint32_t h2u(__half2 h) {
    return *reinterpret_cast<uint32_t*>(&h);
}
__device__ __forceinline__ void cpa16(uint32_t dst, const void* src) {
    asm volatile("cp.async.cg.shared.global [%0], [%1], 16;" :: "r"(dst), "l"(src));
}
__device__ __forceinline__ uint32_t smem_u32(const void* p) {
    uint32_t a;
    asm("{ .reg .u64 t; cvta.to.shared.u64 t, %1; cvt.u32.u64 %0, t; }" : "=r"(a) : "l"(p));
    return a;
}
__device__ __forceinline__ void ldm4(uint32_t addr, uint32_t* r) {
    asm volatile("ldmatrix.sync.aligned.m8n8.x4.shared.b16 {%0,%1,%2,%3}, [%4];"
                 : "=r"(r[0]), "=r"(r[1]), "=r"(r[2]), "=r"(r[3]) : "r"(addr));
}
__device__ __forceinline__ void ldm4t(uint32_t addr, uint32_t* r) {
    asm volatile("ldmatrix.sync.aligned.m8n8.x4.trans.shared.b16 {%0,%1,%2,%3}, [%4];"
                 : "=r"(r[0]), "=r"(r[1]), "=r"(r[2]), "=r"(r[3]) : "r"(addr));
}
#define MMA16816(acc, af, b0, b1) \
    asm volatile( \
        "mma.sync.aligned.m16n8k16.row.col.f32.f16.f16.f32 " \
        "{%0,%1,%2,%3}, {%4,%5,%6,%7}, {%8,%9}, {%0,%1,%2,%3};" \
        : "+f"((acc)[0]), "+f"((acc)[1]), "+f"((acc)[2]), "+f"((acc)[3]) \
        : "r"((af)[0]), "r"((af)[1]), "r"((af)[2]), "r"((af)[3]), \
          "r"(b0), "r"(b1))

// -------- round all 8 f32 weight matrices to fp16 (RN), one launch --------
struct WPtrs { const float* p[8]; };
__global__ void round_h_k(WPtrs w, __half* __restrict__ out) {
    size_t i = (size_t)blockIdx.x * blockDim.x + threadIdx.x;
    int m = (int)(i >> 18);
    int e = (int)(i & 0x3FFFF);
    out[i] = __float2half_rn(w.p[m][e]);
}

// -------- concat(visual, audio) -> dense [BT*NP, H] + half copy --------
__global__ void concat_kernel(const float* __restrict__ vis,
                              const float* __restrict__ aud,
                              float* __restrict__ out,
                              __half* __restrict__ outh) {
    size_t idx = (size_t)blockIdx.x * blockDim.x + threadIdx.x;
    size_t total = (size_t)M_ALL * (Hd/4);
    if (idx >= total) return;
    int h4 = (int)(idx & 127);
    size_t row = idx >> 7;
    int i = (int)(row % NP);
    size_t bt = row / NP;
    float4 v;
    if (i < NV) v = ((const float4*)vis)[(bt*NV + i)*(Hd/4) + h4];
    else        v = ((const float4*)aud)[bt*(Hd/4) + h4];
    ((float4*)out)[idx] = v;
    __half2 h0 = __floats2half2_rn(v.x, v.y);
    __half2 h1 = __floats2half2_rn(v.z, v.w);
    __half2* oh = (__half2*)(outh + idx*4);
    oh[0] = h0; oh[1] = h1;
}

// ============ fp16 mma.sync GEMM, K-chunk 64, 3-stage cp.async ============
#define SROWH 72
#define ASTG_B (128*SROWH*2)
#define NSTAGE 3
#define GH_SMEM (2*NSTAGE*ASTG_B)

__global__ void __launch_bounds__(256, 2) gemm_fp16(
    const __half* __restrict__ A, int amode, int ashift,
    const float* __restrict__ scale, int smode,
    const __half* __restrict__ W,
    const float* __restrict__ bias, int relu_flag,
    const float* __restrict__ add1, int a1mode, int a1shift,
    const float* __restrict__ add2, const __half* __restrict__ add2h,
    float* __restrict__ C, __half* __restrict__ Ch,
    int cmode, int cshift, int M)
{
    extern __shared__ char smraw[];
    const uint32_t sm0 = smem_u32(smraw);
    const int tid  = threadIdx.x;
    const int wid  = tid >> 5;
    const int lane = tid & 31;
    const int tig  = lane & 3;
    const int wm   = wid & 1;
    const int wn   = wid >> 1;
    const int nb   = blockIdx.x;
    const int row0 = blockIdx.y * 128;
    const int g    = lane >> 2;

    const int ar = tid >> 1, ah = tid & 1;
    int gra = row0 + ar; if (gra >= M) gra = M - 1;
    const __half* aptr = A + row_off(gra, amode, ashift) + ah*32;
    const __half* bptr = W + (size_t)(nb*128 + ar)*Hd + ah*32;
    const uint32_t sa_addr = sm0 + (uint32_t)(ar*SROWH + ah*32)*2;
    const uint32_t sb_addr = sm0 + (uint32_t)(NSTAGE*128*SROWH + ar*SROWH + ah*32)*2;

    auto CPAB = [&](int st, int k0) {
        uint32_t so = (uint32_t)st * ASTG_B;
        #pragma unroll
        for (int j = 0; j < 4; j++)
            cpa16(sa_addr + so + j*16, aptr + k0 + j*8);
        #pragma unroll
        for (int j = 0; j < 4; j++)
            cpa16(sb_addr + so + j*16, bptr + k0 + j*8);
        asm volatile("cp.async.commit_group;" ::: "memory");
    };

    uint32_t la[4], lb[2];
    #pragma unroll
    for (int mt = 0; mt < 4; mt++)
        la[mt] = sm0 + (uint32_t)((wm*64 + mt*16 + (lane & 15))*SROWH + (lane >> 4)*8)*2;
    #pragma unroll
    for (int ntp = 0; ntp < 2; ntp++)
        lb[ntp] = sm0 + (uint32_t)(NSTAGE*128*SROWH)*2
                + (uint32_t)((wn*32 + ntp*16 + (lane & 15))*SROWH + (lane >> 4)*8)*2;

    float acc[4][4][4];
    #pragma unroll
    for (int a = 0; a < 4; a++)
        #pragma unroll
        for (int b = 0; b < 4; b++)
            #pragma unroll
            for (int c = 0; c < 4; c++) acc[a][b][c] = 0.f;

    CPAB(0, 0);
    CPAB(1, 64);

    const int NTILES = Hd/64;
    for (int kt = 0; kt < NTILES; kt++) {
        const int st = kt % NSTAGE;
        const uint32_t soff = (uint32_t)st * ASTG_B;
        if (kt + 1 < NTILES) asm volatile("cp.async.wait_group 1;" ::: "memory");
        else                 asm volatile("cp.async.wait_group 0;" ::: "memory");
        __syncthreads();
        // software-pipelined fragment loads: A double-buffered across mt
        uint32_t afc[4], afn[4];
        ldm4(la[0] + soff, afc);
        #pragma unroll
        for (int ks = 0; ks < 4; ks++) {
            const uint32_t kb = soff + ks*32;
            uint32_t bf0[4], bf1[4];
            ldm4(lb[0] + kb, bf0);
            ldm4(lb[1] + kb, bf1);
            #pragma unroll
            for (int mt = 0; mt < 4; mt++) {
                if (mt < 3)      ldm4(la[mt+1] + kb, afn);
                else if (ks < 3) ldm4(la[0] + soff + (ks+1)*32, afn);
                #pragma unroll
                for (int nt = 0; nt < 4; nt++) {
                    const uint32_t* bp = (nt & 2) ? bf1 : bf0;
                    const int sel = nt & 1;
                    MMA16816(acc[mt][nt], afc, bp[sel], bp[sel+2]);
                }
                #pragma unroll
                for (int q = 0; q < 4; q++) { uint32_t t = afc[q]; afc[q] = afn[q]; afn[q] = t; }
            }
        }
        if (kt + 2 < NTILES) CPAB((kt + 2) % NSTAGE, (kt + 2) * 64);
    }

    #pragma unroll
    for (int mt = 0; mt < 4; mt++) {
        #pragma unroll
        for (int hf = 0; hf < 2; hf++) {
            int r = row0 + wm*64 + mt*16 + g + hf*8;
            if (r >= M) continue;
            size_t co  = row_off(r, cmode, cshift);
            size_t a1o = add1 ? row_off(r, a1mode, a1shift) : 0;
            float sc = 1.f;
            if (smode) { float v = scale[r]; sc = (smode == 1) ? v : (1.f - v); }
            #pragma unroll
            for (int nt = 0; nt < 4; nt++) {
                int n = nb*128 + wn*32 + nt*8 + tig*2;
                float vx = acc[mt][nt][hf*2+0];
                float vy = acc[mt][nt][hf*2+1];
                if (smode) { vx *= sc; vy *= sc; }
                if (bias)  { vx += bias[n]; vy += bias[n+1]; }
                if (relu_flag) { vx = fmaxf(vx, 0.f); vy = fmaxf(vy, 0.f); }
                if (add1)  { vx += add1[a1o + n]; vy += add1[a1o + n + 1]; }
                if (add2)  { vx += add2[(size_t)r*Hd + n]; vy += add2[(size_t)r*Hd + n + 1]; }
                if (add2h) {
                    __half2 a2 = *(const __half2*)(add2h + (size_t)r*Hd + n);
                    float2 a2f = __half22float2(a2);
                    vx += a2f.x; vy += a2f.y;
                }
                if (C)  *(float2*)(C + co + n) = make_float2(vx, vy);
                if (Ch) *(__half2*)(Ch + co + n) = __floats2half2_rn(vx, vy);
            }
        }
    }
}

// ============ attn kernel 1: Gram(fp16 mma) + scores + softmax -> S' ============
#define K1_XH   0
#define K1_G    66560                 // 64*520*2
#define K1_S    (K1_G + 64*66*4)      // 83456
#define K1_QN   (K1_S + 50*52*4)      // 94272
#define K1_KN0  (K1_QN + 200)
#define K1_KN1  (K1_KN0 + 196)
#define K1_SAV  (K1_KN1 + 196)
#define K1_A49  (K1_SAV + 200)
#define K1_RED  (K1_A49 + 200)
#define K1_SMEM (K1_RED + 144)
#define GSTR 66

__global__ __launch_bounds__(512, 2) void attn_score_kernel(
    const float* __restrict__ X, const float* __restrict__ edge,
    float* __restrict__ attn_out, __half* __restrict__ Sout)
{
    extern __shared__ char smraw[];
    float*  G  = (float*)(smraw + K1_G);
    float*  S  = (float*)(smraw + K1_S);
    float*  qn = (float*)(smraw + K1_QN);
    float*  kn0= (float*)(smraw + K1_KN0);
    float*  kn1= (float*)(smraw + K1_KN1);
    float*  sAv= (float*)(smraw + K1_SAV);
    float*  a49= (float*)(smraw + K1_A49);
    float*  red= (float*)(smraw + K1_RED);

    const int bt   = blockIdx.x;
    const int tid  = threadIdx.x;
    const int lane = tid & 31, warp = tid >> 5;

    {
        const float4* xg = (const float4*)(X + (size_t)bt*NP*Hd);
        const float4* eg = (const float4*)edge;
        for (int u = tid; u < 64*128; u += 512) {
            int row = u >> 7, c4 = u & 127;
            float4 v;
            if (row < NP)      v = xg[row*128 + c4];
            else if (row < 53) v = eg[(row - NP)*128 + c4];
            else               v = make_float4(0.f, 0.f, 0.f, 0.f);
            uint2 pk;
            pk.x = h2u(__floats2half2_rn(v.x, v.y));
            pk.y = h2u(__floats2half2_rn(v.z, v.w));
            *(uint2*)(smraw + K1_XH + (row*520 + c4*4)*2) = pk;
        }
    }
    __syncthreads();

    {
        const uint32_t xb = smem_u32(smraw) + K1_XH;
        const int wm = warp & 3, wn = warp >> 2;
        uint32_t la = xb + (uint32_t)((wm*16 + (lane & 15))*520 + (lane >> 4)*8)*2;
        uint32_t lb = xb + (uint32_t)((wn*16 + (lane & 15))*520 + (lane >> 4)*8)*2;
        float gacc[2][4];
        #pragma unroll
        for (int a = 0; a < 2; a++)
            #pragma unroll
            for (int b = 0; b < 4; b++) gacc[a][b] = 0.f;
        #pragma unroll 8
        for (int kk = 0; kk < 32; kk++) {
            const uint32_t kb = kk*32;
            uint32_t af[4], bf[4];
            ldm4(la + kb, af);
            ldm4(lb + kb, bf);
            MMA16816(gacc[0], af, bf[0], bf[2]);
            MMA16816(gacc[1], af, bf[1], bf[3]);
        }
        #pragma unroll
        for (int nt = 0; nt < 2; nt++) {
            int gr = wm*16 + (lane >> 2);
            int gc = wn*16 + nt*8 + (lane & 3)*2;
            *(float2*)&G[gr*GSTR + gc]     = make_float2(gacc[nt][0], gacc[nt][1]);
            *(float2*)&G[(gr+8)*GSTR + gc] = make_float2(gacc[nt][2], gacc[nt][3]);
        }
    }
    __syncthreads();

    if (tid < 50) qn[tid] = fmaxf(sqrtf(G[tid*GSTR+tid]), 1e-12f);
    if (tid >= 64 && tid < 64+49) {
        int j = tid - 64;
        kn0[j] = fmaxf(sqrtf(G[j*GSTR+j] + 2.f*G[j*GSTR+50] + G[50*GSTR+50]), 1e-12f);
    }
    if (tid >= 128 && tid < 128+49) {
        int j = tid - 128;
        kn1[j] = fmaxf(sqrtf(G[j*GSTR+j] + 2.f*G[j*GSTR+51] + G[51*GSTR+51]), 1e-12f);
    }
    if (tid == 192)
        red[33] = fmaxf(sqrtf(G[49*GSTR+49] + 2.f*G[49*GSTR+52] + G[52*GSTR+52]), 1e-12f);
    __syncthreads();
    const float kn2 = red[33];

    for (int p = tid; p < 2500; p += 512) {
        int i = p / 50, j = p - (p/50)*50;
        float v;
        if (i == j)       v = NEGV;
        else if (j == 49) v = (G[i*GSTR+49] + G[i*GSTR+52]) / (qn[i]*kn2);
        else if (i == 49) v = (G[49*GSTR+j] + G[49*GSTR+51]) / (qn[49]*kn1[j]);
        else {
            int qr = i/7, qc = i - (i/7)*7, kr = j/7, kc = j - (j/7)*7;
            int r0 = (qr-1 > 0) ? qr-1 : 0;
            int c0 = qc-1; c0 = (c0 < 0) ? 0 : ((c0 > 4) ? 4 : c0);
            bool ok = (kr >= r0 && kr <= r0+2 && kc >= c0 && kc <= c0+2);
            v = ok ? (G[i*GSTR+j] + G[i*GSTR+50]) / (qn[i]*kn0[j]) : NEGV;
        }
        S[i*52+j] = v;
    }
    __syncthreads();

    for (int i = warp; i < 50; i += 16) {
        float v0 = S[i*52 + lane];
        int j1 = lane + 32;
        float v1 = (j1 < 50) ? S[i*52 + j1] : -3.4e38f;
        float m = fmaxf(v0, v1);
        #pragma unroll
        for (int o = 16; o; o >>= 1) m = fmaxf(m, __shfl_xor_sync(0xffffffffu, m, o));
        float e0 = expf(v0 - m);
        float e1 = (j1 < 50) ? expf(v1 - m) : 0.f;
        float s = e0 + e1;
        #pragma unroll
        for (int o = 16; o; o >>= 1) s += __shfl_xor_sync(0xffffffffu, s, o);
        float e49 = __shfl_sync(0xffffffffu, e1, 17);
        float inv = 1.f / s;
        float p0 = e0 * inv, p1 = e1 * inv;
        S[i*52 + lane] = p0;
        if (j1 < 50) S[i*52 + j1] = p1;
        if (lane == 0) { sAv[i] = (s - e49)*inv; a49[i] = e49*inv; }
        if (attn_out) {
            attn_out[((size_t)bt*50 + i)*50 + lane] = p0;
            if (j1 < 50) attn_out[((size_t)bt*50 + i)*50 + j1] = p1;
        }
    }
    __syncthreads();

    __half* sout = Sout + (size_t)bt*4096;
    for (int p = tid; p < 4096; p += 512) {
        int i = p >> 6, j = p & 63;
        float v = 0.f;
        if (i < 50) {
            if (j < 50)       v = S[i*52 + j];
            else if (j == 50) v = (i < 49)  ? sAv[i]  : 0.f;
            else if (j == 51) v = (i == 49) ? sAv[49] : 0.f;
            else if (j == 52) v = a49[i];
        }
        sout[p] = __float2half_rn(v);
    }
}

// ============ attn kernel 2: agg = S' @ X (fp16 mma) + residual + LN ============
#define K2_SH   0                         // 64*72 halves = 9216B
#define K2_XH   9216                      // 64*520 halves = 66560B
#define K2_PART (K2_XH + 66560)           // 64*8 floats = 2048B
#define K2_MU   (K2_PART + 2048)          // 64 floats
#define K2_RS   (K2_MU + 256)             // 64 floats
#define K2_GB   (K2_RS + 256)             // 1024 floats
#define K2_SMEM (K2_GB + 4096)

__global__ __launch_bounds__(512, 1) void agg_ln_kernel(
    const float* __restrict__ X, const float* __restrict__ edge,
    const __half* __restrict__ Sin,
    const float* __restrict__ lng, const float* __restrict__ lnb,
    float* __restrict__ spatial, __half* __restrict__ spatial_h)
{
    extern __shared__ char smraw[];
    float* part = (float*)(smraw + K2_PART);
    float* muA  = (float*)(smraw + K2_MU);
    float* rsA  = (float*)(smraw + K2_RS);
    float* gb   = (float*)(smraw + K2_GB);

    const int bt   = blockIdx.x;
    const int tid  = threadIdx.x;
    const int lane = tid & 31, warp = tid >> 5;
    const int g = lane >> 2, tig = lane & 3;

    {
        const float4* xg = (const float4*)(X + (size_t)bt*NP*Hd);
        const float4* eg = (const float4*)edge;
        for (int u = tid; u < 64*128; u += 512) {
            int row = u >> 7, c4 = u & 127;
            float4 v;
            if (row < NP)      v = xg[row*128 + c4];
            else if (row < 53) v = eg[(row - NP)*128 + c4];
            else               v = make_float4(0.f, 0.f, 0.f, 0.f);
            uint2 pk;
            pk.x = h2u(__floats2half2_rn(v.x, v.y));
            pk.y = h2u(__floats2half2_rn(v.z, v.w));
            *(uint2*)(smraw + K2_XH + (row*520 + c4*4)*2) = pk;
        }
    }
    {
        const uint4* sg = (const uint4*)(Sin + (size_t)bt*4096);
        uint4 v = sg[tid];
        int row = tid >> 3, col8 = (tid & 7)*8;
        *(uint4*)(smraw + K2_SH + (row*72 + col8)*2) = v;
    }
    gb[tid]       = lng[tid];
    gb[512 + tid] = lnb[tid];
    __syncthreads();

    const int wm = warp & 3, wn = warp >> 2;
    const uint32_t sm0 = smem_u32(smraw);
    uint32_t la = sm0 + K2_SH + (uint32_t)((wm*16 + (lane & 15))*72 + (lane >> 4)*8)*2;
    uint32_t lbrow = sm0 + K2_XH
                   + (uint32_t)(((lane & 7) + 8*((lane >> 3) & 1))*520)*2
                   + (uint32_t)((lane >> 4)*8)*2;

    float acc[16][4];
    #pragma unroll
    for (int a = 0; a < 16; a++)
        #pragma unroll
        for (int b = 0; b < 4; b++) acc[a][b] = 0.f;

    #pragma unroll
    for (int kk = 0; kk < 4; kk++) {
        uint32_t af[4];
        ldm4(la + kk*32, af);
        #pragma unroll
        for (int nb2 = 0; nb2 < 8; nb2++) {
            uint32_t bf[4];
            ldm4t(lbrow + (uint32_t)(kk*16*520)*2 + (uint32_t)((wn*128 + nb2*16))*2, bf);
            MMA16816(acc[nb2*2],   af, bf[0], bf[1]);
            MMA16816(acc[nb2*2+1], af, bf[2], bf[3]);
        }
    }

    const int r0g = wm*16 + g, r1g = r0g + 8;
    const float* x0 = X + ((size_t)bt*NP + r0g)*Hd;
    const float* x1 = X + ((size_t)bt*NP + r1g)*Hd;
    float s1a = 0.f, s2a = 0.f, s1b = 0.f, s2b = 0.f;
    #pragma unroll
    for (int nt = 0; nt < 16; nt++) {
        int c = wn*128 + (nt >> 1)*16 + (nt & 1)*8 + tig*2;
        if (r0g < NP) {
            float2 rx = *(const float2*)(x0 + c);
            acc[nt][0] += rx.x; acc[nt][1] += rx.y;
            s1a += acc[nt][0] + acc[nt][1];
            s2a += acc[nt][0]*acc[nt][0] + acc[nt][1]*acc[nt][1];
        }
        if (r1g < NP) {
            float2 rx = *(const float2*)(x1 + c);
            acc[nt][2] += rx.x; acc[nt][3] += rx.y;
            s1b += acc[nt][2] + acc[nt][3];
            s2b += acc[nt][2]*acc[nt][2] + acc[nt][3]*acc[nt][3];
        }
    }
    #pragma unroll
    for (int o = 1; o <= 2; o <<= 1) {
        s1a += __shfl_xor_sync(0xffffffffu, s1a, o);
        s2a += __shfl_xor_sync(0xffffffffu, s2a, o);
        s1b += __shfl_xor_sync(0xffffffffu, s1b, o);
        s2b += __shfl_xor_sync(0xffffffffu, s2b, o);
    }
    if (tig == 0) {
        part[r0g*8 + wn]     = s1a;
        part[r0g*8 + 4 + wn] = s2a;
        part[r1g*8 + wn]     = s1b;
        part[r1g*8 + 4 + wn] = s2b;
    }
    __syncthreads();
    if (tid < 64) {
        float s1 = part[tid*8+0] + part[tid*8+1] + part[tid*8+2] + part[tid*8+3];
        float s2 = part[tid*8+4] + part[tid*8+5] + part[tid*8+6] + part[tid*8+7];
        float mu = s1 * (1.f/512.f);
        muA[tid] = mu;
        rsA[tid] = rsqrtf(s2*(1.f/512.f) - mu*mu + 1e-5f);
    }
    __syncthreads();

    #pragma unroll
    for (int hr = 0; hr < 2; hr++) {
        int r = hr ? r1g : r0g;
        if (r >= NP) continue;
        float mu = muA[r], rs = rsA[r];
        float*  dst  = spatial   + ((size_t)bt*NP + r)*Hd;
        __half* dsth = spatial_h + ((size_t)bt*NP + r)*Hd;
        #pragma unroll
        for (int nt = 0; nt < 16; nt++) {
            int c = wn*128 + (nt >> 1)*16 + (nt & 1)*8 + tig*2;
            float vx = acc[nt][hr*2+0], vy = acc[nt][hr*2+1];
            float ox = fmaxf(0.f, (vx - mu)*rs*gb[c]   + gb[512 + c]);
            float oy = fmaxf(0.f, (vy - mu)*rs*gb[c+1] + gb[512 + c + 1]);
            *(float2*)(dst + c) = make_float2(ox, oy);
            *(__half2*)(dsth + c) = __floats2half2_rn(ox, oy);
        }
    }
}

// -------- cosine between spatial[t] and spatial[t-1] --------
__global__ void cos_kernel(const float* __restrict__ sp,
                           float* __restrict__ c1, float* __restrict__ c2) {
    int gw = (int)((blockIdx.x*(size_t)blockDim.x + threadIdx.x) >> 5);
    int lane = threadIdx.x & 31;
    if (gw >= M_T) return;
    int b   = gw / ((Tt-1)*NP);
    int rem = gw - b*(Tt-1)*NP;
    int tt  = rem / NP;
    int i   = rem - tt*NP;
    const float4* pa = (const float4*)(sp + (((size_t)(b*Tt + tt + 1))*NP + i)*Hd);
    const float4* pb = (const float4*)(sp + (((size_t)(b*Tt + tt))*NP + i)*Hd);
    float d = 0.f, na = 0.f, nb2 = 0.f;
    for (int u = lane; u < 128; u += 32) {
        float4 a = pa[u], c = pb[u];
        d   += a.x*c.x + a.y*c.y + a.z*c.z + a.w*c.w;
        na  += a.x*a.x + a.y*a.y + a.z*a.z + a.w*a.w;
        nb2 += c.x*c.x + c.y*c.y + c.z*c.z + c.w*c.w;
    }
    #pragma unroll
    for (int o = 16; o; o >>= 1) {
        d   += __shfl_xor_sync(0xffffffffu, d, o);
        na  += __shfl_xor_sync(0xffffffffu, na, o);
        nb2 += __shfl_xor_sync(0xffffffffu, nb2, o);
    }
    if (lane == 0) {
        float v = d / (fmaxf(sqrtf(na), 1e-8f) * fmaxf(sqrtf(nb2), 1e-8f));
        c1[gw] = v;
        if (c2) c2[gw] = v;
    }
}

// -------- copy t=0 rows of spatial into z --------
__global__ void copy_t0(const float* __restrict__ sp, float* __restrict__ z) {
    int u = blockIdx.x*blockDim.x + threadIdx.x;
    if (u >= Bsz*NP*(Hd/4)) return;
    int h4 = u & 127;
    int rem = u >> 7;
    int i = rem % NP;
    int b = rem / NP;
    size_t off = ((size_t)(b*Tt)*NP + i)*(Hd/4) + h4;
    ((float4*)z)[off] = ((const float4*)sp)[off];
}

// -------- LayerNorm rows of 512, block per row, dual fp32+fp16 out --------
__global__ __launch_bounds__(512) void ln512(const float* __restrict__ X,
                                             const float* __restrict__ g,
                                             const float* __restrict__ b,
                                             float* __restrict__ Y,
                                             __half* __restrict__ Yh) {
    __shared__ float red[34];
    size_t base = (size_t)blockIdx.x * Hd;
    int tid = threadIdx.x, lane = tid & 31, warp = tid >> 5;
    float v = X[base + tid];
    float s1 = v, s2 = v*v;
    #pragma unroll
    for (int o = 16; o; o >>= 1) {
        s1 += __shfl_xor_sync(0xffffffffu, s1, o);
        s2 += __shfl_xor_sync(0xffffffffu, s2, o);
    }
    if (!lane) { red[warp] = s1; red[16+warp] = s2; }
    __syncthreads();
    if (warp == 0) {
        float a = (lane < 16) ? red[lane]    : 0.f;
        float c = (lane < 16) ? red[16+lane] : 0.f;
        #pragma unroll
        for (int o = 8; o; o >>= 1) {
            a += __shfl_xor_sync(0xffffffffu, a, o);
            c += __shfl_xor_sync(0xffffffffu, c, o);
        }
        if (!lane) {
            float m = a * (1.f/512.f);
            red[32] = m;
            red[33] = rsqrtf(c*(1.f/512.f) - m*m + 1e-5f);
        }
    }
    __syncthreads();
    float o = (v - red[32])*red[33]*g[tid] + b[tid];
    Y[base + tid]  = o;
    Yh[base + tid] = __float2half_rn(o);
}

extern "C" void kernel_launch(void* const* d_in, const int* in_sizes, int n_in,
                              void* d_out, int out_size) {
    (void)in_sizes; (void)n_in; (void)out_size;
    const float* vis   = (const float*)d_in[0];
    const float* aud   = (const float*)d_in[1];
    const float* in_W  = (const float*)d_in[2];
    const float* in_b  = (const float*)d_in[3];
    const float* out_W = (const float*)d_in[4];
    const float* out_b = (const float*)d_in[5];

    float* out      = (float*)d_out;
    float* attn_out = out + (size_t)M_ALL*Hd;
    float* cos_out  = attn_out + (size_t)BT*NP*NP;

    float *gx, *gsp, *gz, *gtmp, *gcos;
    __half *gxh, *gsph, *gzh, *gtmph, *gwh, *gsh;
    cudaGetSymbolAddress((void**)&gx,    g_x);
    cudaGetSymbolAddress((void**)&gsp,   g_sp);
    cudaGetSymbolAddress((void**)&gz,    g_z);
    cudaGetSymbolAddress((void**)&gtmp,  g_tmp);
    cudaGetSymbolAddress((void**)&gcos,  g_cos);
    cudaGetSymbolAddress((void**)&gxh,   g_xh);
    cudaGetSymbolAddress((void**)&gsph,  g_sph);
    cudaGetSymbolAddress((void**)&gzh,   g_zh);
    cudaGetSymbolAddress((void**)&gtmph, g_tmph);
    cudaGetSymbolAddress((void**)&gwh,   g_wh);
    cudaGetSymbolAddress((void**)&gsh,   g_sh);

    cudaFuncSetAttribute(attn_score_kernel,
                         cudaFuncAttributeMaxDynamicSharedMemorySize, K1_SMEM);
    cudaFuncSetAttribute(agg_ln_kernel,
                         cudaFuncAttributeMaxDynamicSharedMemorySize, K2_SMEM);
    cudaFuncSetAttribute(gemm_fp16,
                         cudaFuncAttributeMaxDynamicSharedMemorySize, GH_SMEM);

    WPtrs wp;
    wp.p[0] = in_W;  wp.p[1] = out_W;
    wp.p[2] = (const float*)d_in[9];  wp.p[3] = (const float*)d_in[11];
    wp.p[4] = (const float*)d_in[13]; wp.p[5] = (const float*)d_in[17];
    wp.p[6] = (const float*)d_in[19]; wp.p[7] = (const float*)d_in[21];
    round_h_k<<<8192, 256>>>(wp, gwh);
    const __half* W_in  = gwh;
    const __half* W_out = gwh + (size_t)1*512*512;
    const __half* W_l[2][3] = { { gwh+(size_t)2*512*512, gwh+(size_t)3*512*512, gwh+(size_t)4*512*512 },
                                { gwh+(size_t)5*512*512, gwh+(size_t)6*512*512, gwh+(size_t)7*512*512 } };

    concat_kernel<<<(M_ALL*128 + 255)/256, 256>>>(vis, aud, gz, gzh);
    dim3 gAll(4, (M_ALL + 127)/128);
    gemm_fp16<<<gAll, 256, GH_SMEM>>>(gzh, 0, 0, nullptr, 0, W_in, in_b, 0,
                                      nullptr, 0, 0, nullptr, nullptr,
                                      gx, nullptr, 0, 0, M_ALL);

    for (int L = 0; L < 2; L++) {
        const float* edge = (const float*)d_in[6 + L*8];
        const float* lng  = (const float*)d_in[7 + L*8];
        const float* lnb  = (const float*)d_in[8 + L*8];
        const float* bc   = (const float*)d_in[10 + L*8];
        const float* bs   = (const float*)d_in[12 + L*8];

        attn_score_kernel<<<BT, 512, K1_SMEM>>>(
            gx, edge, (L == 1) ? attn_out : nullptr, gsh);
        agg_ln_kernel<<<BT, 512, K2_SMEM>>>(
            gx, edge, gsh, lng, lnb, gsp, gsph);

        cos_kernel<<<(M_T*32 + 255)/256, 256>>>(gsp, gcos, (L == 1) ? cos_out : nullptr);

        dim3 gT(4, (M_T + 127)/128);
        // tc = relu(cos * (prev @ Wc^T) + bc) -> gtmph (fp16 only)
        gemm_fp16<<<gT, 256, GH_SMEM>>>(gsph, 1, 0, gcos, 1, W_l[L][0], bc, 1,
                                        nullptr, 0, 0, nullptr, nullptr,
                                        nullptr, gtmph, 0, 0, M_T);
        // z[t+1] = cur + tc + relu((1-cos) * (cur @ Ws^T) + bs)
        gemm_fp16<<<gT, 256, GH_SMEM>>>(gsph, 1, 1, gcos, 2, W_l[L][1], bs, 1,
                                        gsp, 1, 1, nullptr, gtmph,
                                        gz, nullptr, 1, 1, M_T);
        copy_t0<<<(Bsz*NP*128 + 255)/256, 256>>>(gsp, gz);

        ln512<<<M_ALL, 512>>>(gz, lng, lnb, gtmp, gtmph);
        gemm_fp16<<<gAll, 256, GH_SMEM>>>(gtmph, 0, 0, nullptr, 0, W_l[L][2], nullptr, 1,
                                          gx, 0, 0, nullptr, nullptr,
                                          gx, (L == 1) ? gxh : nullptr, 0, 0, M_ALL);
    }

    gemm_fp16<<<gAll, 256, GH_SMEM>>>(gxh, 0, 0, nullptr, 0, W_out, out_b, 0,
                                      nullptr, 0, 0, nullptr, nullptr,
                                      out, nullptr, 0, 0, M_ALL);
}

// round 14
// speedup vs baseline: 1.7720x; 1.1620x over previous
#include <cuda_runtime.h>
#include <cuda_fp16.h>
#include <math.h>
#include <cstdint>

#define Bsz 16
#define Tt 64
#define NV 49
#define NP 50
#define Hd 512
#define BT (Bsz*Tt)              // 1024
#define M_ALL (BT*NP)            // 51200
#define M_T (Bsz*(Tt-1)*NP)      // 50400
#define NEGV (-1000000000.0f)

// -------- static device scratch (no allocations allowed) --------
__device__ float g_x[(size_t)M_ALL*Hd];
__device__ float g_sp[(size_t)M_ALL*Hd];
__device__ float g_z[(size_t)M_ALL*Hd];
__device__ float g_cos[M_T];
__device__ __half g_xh[(size_t)M_ALL*Hd];
__device__ __half g_sph[(size_t)M_ALL*Hd];
__device__ __half g_zh[(size_t)M_ALL*Hd];
__device__ __half g_tmph[(size_t)M_ALL*Hd];
__device__ __half g_wh[8][512*512];   // fp16-rounded weights
__device__ __half g_sh[(size_t)BT*64*64];  // per-(b,t) S' matrices (fp16)

__device__ __forceinline__ size_t row_off(int r, int mode, int shift) {
    if (mode == 0) return (size_t)r * Hd;
    int b   = r / ((Tt-1)*NP);
    int rem = r - b*(Tt-1)*NP;
    int tt  = rem / NP;
    int i   = rem - tt*NP;
    return ((size_t)((b*Tt + tt + shift)*NP) + i) * Hd;
}

__device__ __forceinline__ uint32_t h2u(__half2 h) {
    return *reinterpret_cast<uint32_t*>(&h);
}
__device__ __forceinline__ void cpa16(uint32_t dst, const void* src) {
    asm volatile("cp.async.cg.shared.global [%0], [%1], 16;" :: "r"(dst), "l"(src));
}
__device__ __forceinline__ uint32_t smem_u32(const void* p) {
    uint32_t a;
    asm("{ .reg .u64 t; cvta.to.shared.u64 t, %1; cvt.u32.u64 %0, t; }" : "=r"(a) : "l"(p));
    return a;
}
__device__ __forceinline__ void ldm4(uint32_t addr, uint32_t* r) {
    asm volatile("ldmatrix.sync.aligned.m8n8.x4.shared.b16 {%0,%1,%2,%3}, [%4];"
                 : "=r"(r[0]), "=r"(r[1]), "=r"(r[2]), "=r"(r[3]) : "r"(addr));
}
__device__ __forceinline__ void ldm4t(uint32_t addr, uint32_t* r) {
    asm volatile("ldmatrix.sync.aligned.m8n8.x4.trans.shared.b16 {%0,%1,%2,%3}, [%4];"
                 : "=r"(r[0]), "=r"(r[1]), "=r"(r[2]), "=r"(r[3]) : "r"(addr));
}
#define MMA16816(acc, af, b0, b1) \
    asm volatile( \
        "mma.sync.aligned.m16n8k16.row.col.f32.f16.f16.f32 " \
        "{%0,%1,%2,%3}, {%4,%5,%6,%7}, {%8,%9}, {%0,%1,%2,%3};" \
        : "+f"((acc)[0]), "+f"((acc)[1]), "+f"((acc)[2]), "+f"((acc)[3]) \
        : "r"((af)[0]), "r"((af)[1]), "r"((af)[2]), "r"((af)[3]), \
          "r"(b0), "r"(b1))

// -------- round all 8 f32 weight matrices to fp16 (RN), one launch --------
struct WPtrs { const float* p[8]; };
__global__ void round_h_k(WPtrs w, __half* __restrict__ out) {
    size_t i = (size_t)blockIdx.x * blockDim.x + threadIdx.x;
    int m = (int)(i >> 18);
    int e = (int)(i & 0x3FFFF);
    out[i] = __float2half_rn(w.p[m][e]);
}

// -------- concat(visual, audio) -> fp16 dense [BT*NP, H] --------
__global__ void concat_kernel(const float* __restrict__ vis,
                              const float* __restrict__ aud,
                              __half* __restrict__ outh) {
    size_t idx = (size_t)blockIdx.x * blockDim.x + threadIdx.x;
    size_t total = (size_t)M_ALL * (Hd/4);
    if (idx >= total) return;
    int h4 = (int)(idx & 127);
    size_t row = idx >> 7;
    int i = (int)(row % NP);
    size_t bt = row / NP;
    float4 v;
    if (i < NV) v = ((const float4*)vis)[(bt*NV + i)*(Hd/4) + h4];
    else        v = ((const float4*)aud)[bt*(Hd/4) + h4];
    uint2 pk;
    pk.x = h2u(__floats2half2_rn(v.x, v.y));
    pk.y = h2u(__floats2half2_rn(v.z, v.w));
    *(uint2*)(outh + idx*4) = pk;
}

// ============ fp16 mma.sync GEMM, K-chunk 32, 5-stage cp.async ============
#define KC 32
#define SROWH 40                  // halves per smem row (32 data + 8 pad)
#define STG (128*SROWH*2)         // 10240 bytes per matrix per stage
#define NSTAGE 5
#define GH_SMEM (2*NSTAGE*STG)    // 102400 bytes

__global__ void __launch_bounds__(256, 2) gemm_fp16(
    const __half* __restrict__ A, int amode, int ashift,
    const float* __restrict__ scale, int smode,
    const __half* __restrict__ W,
    const float* __restrict__ bias, int relu_flag,
    const float* __restrict__ add1, int a1mode, int a1shift,
    const float* __restrict__ add2, const __half* __restrict__ add2h,
    float* __restrict__ C, __half* __restrict__ Ch,
    int cmode, int cshift, int M)
{
    extern __shared__ char smraw[];
    const uint32_t sm0 = smem_u32(smraw);
    const int tid  = threadIdx.x;
    const int wid  = tid >> 5;
    const int lane = tid & 31;
    const int tig  = lane & 3;
    const int wm   = wid & 1;
    const int wn   = wid >> 1;
    const int nb   = blockIdx.x;
    const int row0 = blockIdx.y * 128;
    const int g    = lane >> 2;

    const int ar = tid >> 1, ah = tid & 1;
    int gra = row0 + ar; if (gra >= M) gra = M - 1;
    const __half* aptr = A + row_off(gra, amode, ashift) + ah*16;
    const __half* bptr = W + (size_t)(nb*128 + ar)*Hd + ah*16;
    const uint32_t sa_addr = sm0 + (uint32_t)(ar*SROWH + ah*16)*2;
    const uint32_t sb_addr = sm0 + (uint32_t)(NSTAGE*128*SROWH + ar*SROWH + ah*16)*2;

    auto CPAB = [&](int st, int k0) {   // k0 in halves
        uint32_t so = (uint32_t)st * STG;
        #pragma unroll
        for (int j = 0; j < 2; j++)
            cpa16(sa_addr + so + j*16, aptr + k0 + j*8);
        #pragma unroll
        for (int j = 0; j < 2; j++)
            cpa16(sb_addr + so + j*16, bptr + k0 + j*8);
        asm volatile("cp.async.commit_group;" ::: "memory");
    };

    uint32_t la[4], lb[2];
    #pragma unroll
    for (int mt = 0; mt < 4; mt++)
        la[mt] = sm0 + (uint32_t)((wm*64 + mt*16 + (lane & 15))*SROWH + (lane >> 4)*8)*2;
    #pragma unroll
    for (int ntp = 0; ntp < 2; ntp++)
        lb[ntp] = sm0 + (uint32_t)(NSTAGE*128*SROWH)*2
                + (uint32_t)((wn*32 + ntp*16 + (lane & 15))*SROWH + (lane >> 4)*8)*2;

    float acc[4][4][4];
    #pragma unroll
    for (int a = 0; a < 4; a++)
        #pragma unroll
        for (int b = 0; b < 4; b++)
            #pragma unroll
            for (int c = 0; c < 4; c++) acc[a][b][c] = 0.f;

    CPAB(0, 0);
    CPAB(1, KC);
    CPAB(2, 2*KC);
    CPAB(3, 3*KC);

    const int NT = Hd/KC;   // 16
    for (int kt = 0; kt < NT; kt++) {
        asm volatile("cp.async.wait_group 3;" ::: "memory");
        __syncthreads();
        const int st = kt % NSTAGE;
        const uint32_t soff = (uint32_t)st * STG;
        #pragma unroll
        for (int ks = 0; ks < 2; ks++) {
            const uint32_t kb = soff + ks*32;    // k16 = 32 bytes
            uint32_t bf0[4], bf1[4];
            ldm4(lb[0] + kb, bf0);
            ldm4(lb[1] + kb, bf1);
            #pragma unroll
            for (int mt = 0; mt < 4; mt++) {
                uint32_t af[4];
                ldm4(la[mt] + kb, af);
                #pragma unroll
                for (int nt = 0; nt < 4; nt++) {
                    const uint32_t* bp = (nt & 2) ? bf1 : bf0;
                    const int sel = nt & 1;
                    MMA16816(acc[mt][nt], af, bp[sel], bp[sel+2]);
                }
            }
        }
        if (kt + 4 < NT) CPAB((kt + 4) % NSTAGE, (kt + 4) * KC);
        else asm volatile("cp.async.commit_group;" ::: "memory");  // keep group count uniform
    }

    #pragma unroll
    for (int mt = 0; mt < 4; mt++) {
        #pragma unroll
        for (int hf = 0; hf < 2; hf++) {
            int r = row0 + wm*64 + mt*16 + g + hf*8;
            if (r >= M) continue;
            size_t co  = row_off(r, cmode, cshift);
            size_t a1o = add1 ? row_off(r, a1mode, a1shift) : 0;
            float sc = 1.f;
            if (smode) { float v = scale[r]; sc = (smode == 1) ? v : (1.f - v); }
            #pragma unroll
            for (int nt = 0; nt < 4; nt++) {
                int n = nb*128 + wn*32 + nt*8 + tig*2;
                float vx = acc[mt][nt][hf*2+0];
                float vy = acc[mt][nt][hf*2+1];
                if (smode) { vx *= sc; vy *= sc; }
                if (bias)  { vx += bias[n]; vy += bias[n+1]; }
                if (relu_flag) { vx = fmaxf(vx, 0.f); vy = fmaxf(vy, 0.f); }
                if (add1)  { vx += add1[a1o + n]; vy += add1[a1o + n + 1]; }
                if (add2)  { vx += add2[(size_t)r*Hd + n]; vy += add2[(size_t)r*Hd + n + 1]; }
                if (add2h) {
                    __half2 a2 = *(const __half2*)(add2h + (size_t)r*Hd + n);
                    float2 a2f = __half22float2(a2);
                    vx += a2f.x; vy += a2f.y;
                }
                if (C)  *(float2*)(C + co + n) = make_float2(vx, vy);
                if (Ch) *(__half2*)(Ch + co + n) = __floats2half2_rn(vx, vy);
            }
        }
    }
}

// ============ attn kernel 1: Gram(fp16 mma) + scores + softmax -> S' ============
#define K1_XH   0
#define K1_G    66560                 // 64*520*2
#define K1_S    (K1_G + 64*66*4)      // 83456
#define K1_QN   (K1_S + 50*52*4)      // 94272
#define K1_KN0  (K1_QN + 200)
#define K1_KN1  (K1_KN0 + 196)
#define K1_SAV  (K1_KN1 + 196)
#define K1_A49  (K1_SAV + 200)
#define K1_RED  (K1_A49 + 200)
#define K1_SMEM (K1_RED + 144)
#define GSTR 66

__global__ __launch_bounds__(512, 2) void attn_score_kernel(
    const float* __restrict__ X, const float* __restrict__ edge,
    float* __restrict__ attn_out, __half* __restrict__ Sout)
{
    extern __shared__ char smraw[];
    float*  G  = (float*)(smraw + K1_G);
    float*  S  = (float*)(smraw + K1_S);
    float*  qn = (float*)(smraw + K1_QN);
    float*  kn0= (float*)(smraw + K1_KN0);
    float*  kn1= (float*)(smraw + K1_KN1);
    float*  sAv= (float*)(smraw + K1_SAV);
    float*  a49= (float*)(smraw + K1_A49);
    float*  red= (float*)(smraw + K1_RED);

    const int bt   = blockIdx.x;
    const int tid  = threadIdx.x;
    const int lane = tid & 31, warp = tid >> 5;

    {
        const float4* xg = (const float4*)(X + (size_t)bt*NP*Hd);
        const float4* eg = (const float4*)edge;
        for (int u = tid; u < 64*128; u += 512) {
            int row = u >> 7, c4 = u & 127;
            float4 v;
            if (row < NP)      v = xg[row*128 + c4];
            else if (row < 53) v = eg[(row - NP)*128 + c4];
            else               v = make_float4(0.f, 0.f, 0.f, 0.f);
            uint2 pk;
            pk.x = h2u(__floats2half2_rn(v.x, v.y));
            pk.y = h2u(__floats2half2_rn(v.z, v.w));
            *(uint2*)(smraw + K1_XH + (row*520 + c4*4)*2) = pk;
        }
    }
    __syncthreads();

    {
        const uint32_t xb = smem_u32(smraw) + K1_XH;
        const int wm = warp & 3, wn = warp >> 2;
        uint32_t la = xb + (uint32_t)((wm*16 + (lane & 15))*520 + (lane >> 4)*8)*2;
        uint32_t lb = xb + (uint32_t)((wn*16 + (lane & 15))*520 + (lane >> 4)*8)*2;
        float gacc[2][4];
        #pragma unroll
        for (int a = 0; a < 2; a++)
            #pragma unroll
            for (int b = 0; b < 4; b++) gacc[a][b] = 0.f;
        #pragma unroll 8
        for (int kk = 0; kk < 32; kk++) {
            const uint32_t kb = kk*32;
            uint32_t af[4], bf[4];
            ldm4(la + kb, af);
            ldm4(lb + kb, bf);
            MMA16816(gacc[0], af, bf[0], bf[2]);
            MMA16816(gacc[1], af, bf[1], bf[3]);
        }
        #pragma unroll
        for (int nt = 0; nt < 2; nt++) {
            int gr = wm*16 + (lane >> 2);
            int gc = wn*16 + nt*8 + (lane & 3)*2;
            *(float2*)&G[gr*GSTR + gc]     = make_float2(gacc[nt][0], gacc[nt][1]);
            *(float2*)&G[(gr+8)*GSTR + gc] = make_float2(gacc[nt][2], gacc[nt][3]);
        }
    }
    __syncthreads();

    if (tid < 50) qn[tid] = fmaxf(sqrtf(G[tid*GSTR+tid]), 1e-12f);
    if (tid >= 64 && tid < 64+49) {
        int j = tid - 64;
        kn0[j] = fmaxf(sqrtf(G[j*GSTR+j] + 2.f*G[j*GSTR+50] + G[50*GSTR+50]), 1e-12f);
    }
    if (tid >= 128 && tid < 128+49) {
        int j = tid - 128;
        kn1[j] = fmaxf(sqrtf(G[j*GSTR+j] + 2.f*G[j*GSTR+51] + G[51*GSTR+51]), 1e-12f);
    }
    if (tid == 192)
        red[33] = fmaxf(sqrtf(G[49*GSTR+49] + 2.f*G[49*GSTR+52] + G[52*GSTR+52]), 1e-12f);
    __syncthreads();
    const float kn2 = red[33];

    for (int p = tid; p < 2500; p += 512) {
        int i = p / 50, j = p - (p/50)*50;
        float v;
        if (i == j)       v = NEGV;
        else if (j == 49) v = (G[i*GSTR+49] + G[i*GSTR+52]) / (qn[i]*kn2);
        else if (i == 49) v = (G[49*GSTR+j] + G[49*GSTR+51]) / (qn[49]*kn1[j]);
        else {
            int qr = i/7, qc = i - (i/7)*7, kr = j/7, kc = j - (j/7)*7;
            int r0 = (qr-1 > 0) ? qr-1 : 0;
            int c0 = qc-1; c0 = (c0 < 0) ? 0 : ((c0 > 4) ? 4 : c0);
            bool ok = (kr >= r0 && kr <= r0+2 && kc >= c0 && kc <= c0+2);
            v = ok ? (G[i*GSTR+j] + G[i*GSTR+50]) / (qn[i]*kn0[j]) : NEGV;
        }
        S[i*52+j] = v;
    }
    __syncthreads();

    for (int i = warp; i < 50; i += 16) {
        float v0 = S[i*52 + lane];
        int j1 = lane + 32;
        float v1 = (j1 < 50) ? S[i*52 + j1] : -3.4e38f;
        float m = fmaxf(v0, v1);
        #pragma unroll
        for (int o = 16; o; o >>= 1) m = fmaxf(m, __shfl_xor_sync(0xffffffffu, m, o));
        float e0 = expf(v0 - m);
        float e1 = (j1 < 50) ? expf(v1 - m) : 0.f;
        float s = e0 + e1;
        #pragma unroll
        for (int o = 16; o; o >>= 1) s += __shfl_xor_sync(0xffffffffu, s, o);
        float e49 = __shfl_sync(0xffffffffu, e1, 17);
        float inv = 1.f / s;
        float p0 = e0 * inv, p1 = e1 * inv;
        S[i*52 + lane] = p0;
        if (j1 < 50) S[i*52 + j1] = p1;
        if (lane == 0) { sAv[i] = (s - e49)*inv; a49[i] = e49*inv; }
        if (attn_out) {
            attn_out[((size_t)bt*50 + i)*50 + lane] = p0;
            if (j1 < 50) attn_out[((size_t)bt*50 + i)*50 + j1] = p1;
        }
    }
    __syncthreads();

    __half* sout = Sout + (size_t)bt*4096;
    for (int p = tid; p < 4096; p += 512) {
        int i = p >> 6, j = p & 63;
        float v = 0.f;
        if (i < 50) {
            if (j < 50)       v = S[i*52 + j];
            else if (j == 50) v = (i < 49)  ? sAv[i]  : 0.f;
            else if (j == 51) v = (i == 49) ? sAv[49] : 0.f;
            else if (j == 52) v = a49[i];
        }
        sout[p] = __float2half_rn(v);
    }
}

// ============ attn kernel 2: agg = S' @ X (fp16 mma) + residual + LN ============
#define K2_SH   0
#define K2_XH   9216
#define K2_PART (K2_XH + 66560)
#define K2_MU   (K2_PART + 2048)
#define K2_RS   (K2_MU + 256)
#define K2_GB   (K2_RS + 256)
#define K2_SMEM (K2_GB + 4096)

__global__ __launch_bounds__(512, 1) void agg_ln_kernel(
    const float* __restrict__ X, const float* __restrict__ edge,
    const __half* __restrict__ Sin,
    const float* __restrict__ lng, const float* __restrict__ lnb,
    float* __restrict__ spatial, __half* __restrict__ spatial_h)
{
    extern __shared__ char smraw[];
    float* part = (float*)(smraw + K2_PART);
    float* muA  = (float*)(smraw + K2_MU);
    float* rsA  = (float*)(smraw + K2_RS);
    float* gb   = (float*)(smraw + K2_GB);

    const int bt   = blockIdx.x;
    const int tid  = threadIdx.x;
    const int lane = tid & 31, warp = tid >> 5;
    const int g = lane >> 2, tig = lane & 3;

    {
        const float4* xg = (const float4*)(X + (size_t)bt*NP*Hd);
        const float4* eg = (const float4*)edge;
        for (int u = tid; u < 64*128; u += 512) {
            int row = u >> 7, c4 = u & 127;
            float4 v;
            if (row < NP)      v = xg[row*128 + c4];
            else if (row < 53) v = eg[(row - NP)*128 + c4];
            else               v = make_float4(0.f, 0.f, 0.f, 0.f);
            uint2 pk;
            pk.x = h2u(__floats2half2_rn(v.x, v.y));
            pk.y = h2u(__floats2half2_rn(v.z, v.w));
            *(uint2*)(smraw + K2_XH + (row*520 + c4*4)*2) = pk;
        }
    }
    {
        const uint4* sg = (const uint4*)(Sin + (size_t)bt*4096);
        uint4 v = sg[tid];
        int row = tid >> 3, col8 = (tid & 7)*8;
        *(uint4*)(smraw + K2_SH + (row*72 + col8)*2) = v;
    }
    gb[tid]       = lng[tid];
    gb[512 + tid] = lnb[tid];
    __syncthreads();

    const int wm = warp & 3, wn = warp >> 2;
    const uint32_t sm0 = smem_u32(smraw);
    uint32_t la = sm0 + K2_SH + (uint32_t)((wm*16 + (lane & 15))*72 + (lane >> 4)*8)*2;
    uint32_t lbrow = sm0 + K2_XH
                   + (uint32_t)(((lane & 7) + 8*((lane >> 3) & 1))*520)*2
                   + (uint32_t)((lane >> 4)*8)*2;

    float acc[16][4];
    #pragma unroll
    for (int a = 0; a < 16; a++)
        #pragma unroll
        for (int b = 0; b < 4; b++) acc[a][b] = 0.f;

    #pragma unroll
    for (int kk = 0; kk < 4; kk++) {
        uint32_t af[4];
        ldm4(la + kk*32, af);
        #pragma unroll
        for (int nb2 = 0; nb2 < 8; nb2++) {
            uint32_t bf[4];
            ldm4t(lbrow + (uint32_t)(kk*16*520)*2 + (uint32_t)((wn*128 + nb2*16))*2, bf);
            MMA16816(acc[nb2*2],   af, bf[0], bf[1]);
            MMA16816(acc[nb2*2+1], af, bf[2], bf[3]);
        }
    }

    const int r0g = wm*16 + g, r1g = r0g + 8;
    const float* x0 = X + ((size_t)bt*NP + r0g)*Hd;
    const float* x1 = X + ((size_t)bt*NP + r1g)*Hd;
    float s1a = 0.f, s2a = 0.f, s1b = 0.f, s2b = 0.f;
    #pragma unroll
    for (int nt = 0; nt < 16; nt++) {
        int c = wn*128 + (nt >> 1)*16 + (nt & 1)*8 + tig*2;
        if (r0g < NP) {
            float2 rx = *(const float2*)(x0 + c);
            acc[nt][0] += rx.x; acc[nt][1] += rx.y;
            s1a += acc[nt][0] + acc[nt][1];
            s2a += acc[nt][0]*acc[nt][0] + acc[nt][1]*acc[nt][1];
        }
        if (r1g < NP) {
            float2 rx = *(const float2*)(x1 + c);
            acc[nt][2] += rx.x; acc[nt][3] += rx.y;
            s1b += acc[nt][2] + acc[nt][3];
            s2b += acc[nt][2]*acc[nt][2] + acc[nt][3]*acc[nt][3];
        }
    }
    #pragma unroll
    for (int o = 1; o <= 2; o <<= 1) {
        s1a += __shfl_xor_sync(0xffffffffu, s1a, o);
        s2a += __shfl_xor_sync(0xffffffffu, s2a, o);
        s1b += __shfl_xor_sync(0xffffffffu, s1b, o);
        s2b += __shfl_xor_sync(0xffffffffu, s2b, o);
    }
    if (tig == 0) {
        part[r0g*8 + wn]     = s1a;
        part[r0g*8 + 4 + wn] = s2a;
        part[r1g*8 + wn]     = s1b;
        part[r1g*8 + 4 + wn] = s2b;
    }
    __syncthreads();
    if (tid < 64) {
        float s1 = part[tid*8+0] + part[tid*8+1] + part[tid*8+2] + part[tid*8+3];
        float s2 = part[tid*8+4] + part[tid*8+5] + part[tid*8+6] + part[tid*8+7];
        float mu = s1 * (1.f/512.f);
        muA[tid] = mu;
        rsA[tid] = rsqrtf(s2*(1.f/512.f) - mu*mu + 1e-5f);
    }
    __syncthreads();

    #pragma unroll
    for (int hr = 0; hr < 2; hr++) {
        int r = hr ? r1g : r0g;
        if (r >= NP) continue;
        float mu = muA[r], rs = rsA[r];
        float*  dst  = spatial   + ((size_t)bt*NP + r)*Hd;
        __half* dsth = spatial_h + ((size_t)bt*NP + r)*Hd;
        #pragma unroll
        for (int nt = 0; nt < 16; nt++) {
            int c = wn*128 + (nt >> 1)*16 + (nt & 1)*8 + tig*2;
            float vx = acc[nt][hr*2+0], vy = acc[nt][hr*2+1];
            float ox = fmaxf(0.f, (vx - mu)*rs*gb[c]   + gb[512 + c]);
            float oy = fmaxf(0.f, (vy - mu)*rs*gb[c+1] + gb[512 + c + 1]);
            *(float2*)(dst + c) = make_float2(ox, oy);
            *(__half2*)(dsth + c) = __floats2half2_rn(ox, oy);
        }
    }
}

// -------- cosine between spatial[t] and spatial[t-1] --------
__global__ void cos_kernel(const float* __restrict__ sp,
                           float* __restrict__ c1, float* __restrict__ c2) {
    int gw = (int)((blockIdx.x*(size_t)blockDim.x + threadIdx.x) >> 5);
    int lane = threadIdx.x & 31;
    if (gw >= M_T) return;
    int b   = gw / ((Tt-1)*NP);
    int rem = gw - b*(Tt-1)*NP;
    int tt  = rem / NP;
    int i   = rem - tt*NP;
    const float4* pa = (const float4*)(sp + (((size_t)(b*Tt + tt + 1))*NP + i)*Hd);
    const float4* pb = (const float4*)(sp + (((size_t)(b*Tt + tt))*NP + i)*Hd);
    float d = 0.f, na = 0.f, nb2 = 0.f;
    for (int u = lane; u < 128; u += 32) {
        float4 a = pa[u], c = pb[u];
        d   += a.x*c.x + a.y*c.y + a.z*c.z + a.w*c.w;
        na  += a.x*a.x + a.y*a.y + a.z*a.z + a.w*a.w;
        nb2 += c.x*c.x + c.y*c.y + c.z*c.z + c.w*c.w;
    }
    #pragma unroll
    for (int o = 16; o; o >>= 1) {
        d   += __shfl_xor_sync(0xffffffffu, d, o);
        na  += __shfl_xor_sync(0xffffffffu, na, o);
        nb2 += __shfl_xor_sync(0xffffffffu, nb2, o);
    }
    if (lane == 0) {
        float v = d / (fmaxf(sqrtf(na), 1e-8f) * fmaxf(sqrtf(nb2), 1e-8f));
        c1[gw] = v;
        if (c2) c2[gw] = v;
    }
}

// -------- copy t=0 rows of spatial into z --------
__global__ void copy_t0(const float* __restrict__ sp, float* __restrict__ z) {
    int u = blockIdx.x*blockDim.x + threadIdx.x;
    if (u >= Bsz*NP*(Hd/4)) return;
    int h4 = u & 127;
    int rem = u >> 7;
    int i = rem % NP;
    int b = rem / NP;
    size_t off = ((size_t)(b*Tt)*NP + i)*(Hd/4) + h4;
    ((float4*)z)[off] = ((const float4*)sp)[off];
}

// -------- LayerNorm: 4 rows per 512-thread block, float4, fp16-only out ------
__global__ __launch_bounds__(512) void ln512(const float* __restrict__ X,
                                             const float* __restrict__ g,
                                             const float* __restrict__ b,
                                             __half* __restrict__ Yh) {
    __shared__ float red[4][8];
    const int tid  = threadIdx.x;
    const int lr   = tid >> 7;          // 0..3 local row
    const int c    = tid & 127;         // float4 index within row
    const int wig  = c >> 5;            // warp within row group
    const int lane = tid & 31;
    const size_t row = (size_t)blockIdx.x*4 + lr;
    float4 v = ((const float4*)X)[row*128 + c];
    float s1 = v.x + v.y + v.z + v.w;
    float s2 = v.x*v.x + v.y*v.y + v.z*v.z + v.w*v.w;
    #pragma unroll
    for (int o = 16; o; o >>= 1) {
        s1 += __shfl_xor_sync(0xffffffffu, s1, o);
        s2 += __shfl_xor_sync(0xffffffffu, s2, o);
    }
    if (lane == 0) { red[lr][wig] = s1; red[lr][4+wig] = s2; }
    __syncthreads();
    float t1 = red[lr][0] + red[lr][1] + red[lr][2] + red[lr][3];
    float t2 = red[lr][4] + red[lr][5] + red[lr][6] + red[lr][7];
    float mu = t1 * (1.f/512.f);
    float rs = rsqrtf(t2*(1.f/512.f) - mu*mu + 1e-5f);
    float4 gv = ((const float4*)g)[c];
    float4 bv = ((const float4*)b)[c];
    float o0 = (v.x - mu)*rs*gv.x + bv.x;
    float o1 = (v.y - mu)*rs*gv.y + bv.y;
    float o2 = (v.z - mu)*rs*gv.z + bv.z;
    float o3 = (v.w - mu)*rs*gv.w + bv.w;
    uint2 pk;
    pk.x = h2u(__floats2half2_rn(o0, o1));
    pk.y = h2u(__floats2half2_rn(o2, o3));
    *(uint2*)(Yh + row*512 + c*4) = pk;
}

extern "C" void kernel_launch(void* const* d_in, const int* in_sizes, int n_in,
                              void* d_out, int out_size) {
    (void)in_sizes; (void)n_in; (void)out_size;
    const float* vis   = (const float*)d_in[0];
    const float* aud   = (const float*)d_in[1];
    const float* in_W  = (const float*)d_in[2];
    const float* in_b  = (const float*)d_in[3];
    const float* out_W = (const float*)d_in[4];
    const float* out_b = (const float*)d_in[5];

    float* out      = (float*)d_out;
    float* attn_out = out + (size_t)M_ALL*Hd;
    float* cos_out  = attn_out + (size_t)BT*NP*NP;

    float *gx, *gsp, *gz, *gcos;
    __half *gxh, *gsph, *gzh, *gtmph, *gwh, *gsh;
    cudaGetSymbolAddress((void**)&gx,    g_x);
    cudaGetSymbolAddress((void**)&gsp,   g_sp);
    cudaGetSymbolAddress((void**)&gz,    g_z);
    cudaGetSymbolAddress((void**)&gcos,  g_cos);
    cudaGetSymbolAddress((void**)&gxh,   g_xh);
    cudaGetSymbolAddress((void**)&gsph,  g_sph);
    cudaGetSymbolAddress((void**)&gzh,   g_zh);
    cudaGetSymbolAddress((void**)&gtmph, g_tmph);
    cudaGetSymbolAddress((void**)&gwh,   g_wh);
    cudaGetSymbolAddress((void**)&gsh,   g_sh);

    cudaFuncSetAttribute(attn_score_kernel,
                         cudaFuncAttributeMaxDynamicSharedMemorySize, K1_SMEM);
    cudaFuncSetAttribute(agg_ln_kernel,
                         cudaFuncAttributeMaxDynamicSharedMemorySize, K2_SMEM);
    cudaFuncSetAttribute(gemm_fp16,
                         cudaFuncAttributeMaxDynamicSharedMemorySize, GH_SMEM);

    WPtrs wp;
    wp.p[0] = in_W;  wp.p[1] = out_W;
    wp.p[2] = (const float*)d_in[9];  wp.p[3] = (const float*)d_in[11];
    wp.p[4] = (const float*)d_in[13]; wp.p[5] = (const float*)d_in[17];
    wp.p[6] = (const float*)d_in[19]; wp.p[7] = (const float*)d_in[21];
    round_h_k<<<8192, 256>>>(wp, gwh);
    const __half* W_in  = gwh;
    const __half* W_out = gwh + (size_t)1*512*512;
    const __half* W_l[2][3] = { { gwh+(size_t)2*512*512, gwh+(size_t)3*512*512, gwh+(size_t)4*512*512 },
                                { gwh+(size_t)5*512*512, gwh+(size_t)6*512*512, gwh+(size_t)7*512*512 } };

    concat_kernel<<<(M_ALL*128 + 255)/256, 256>>>(vis, aud, gzh);
    dim3 gAll(4, (M_ALL + 127)/128);
    gemm_fp16<<<gAll, 256, GH_SMEM>>>(gzh, 0, 0, nullptr, 0, W_in, in_b, 0,
                                      nullptr, 0, 0, nullptr, nullptr,
                                      gx, nullptr, 0, 0, M_ALL);

    for (int L = 0; L < 2; L++) {
        const float* edge = (const float*)d_in[6 + L*8];
        const float* lng  = (const float*)d_in[7 + L*8];
        const float* lnb  = (const float*)d_in[8 + L*8];
        const float* bc   = (const float*)d_in[10 + L*8];
        const float* bs   = (const float*)d_in[12 + L*8];

        attn_score_kernel<<<BT, 512, K1_SMEM>>>(
            gx, edge, (L == 1) ? attn_out : nullptr, gsh);
        agg_ln_kernel<<<BT, 512, K2_SMEM>>>(
            gx, edge, gsh, lng, lnb, gsp, gsph);

        cos_kernel<<<(M_T*32 + 255)/256, 256>>>(gsp, gcos, (L == 1) ? cos_out : nullptr);

        dim3 gT(4, (M_T + 127)/128);
        // tc = relu(cos * (prev @ Wc^T) + bc) -> gtmph (fp16 only)
        gemm_fp16<<<gT, 256, GH_SMEM>>>(gsph, 1, 0, gcos, 1, W_l[L][0], bc, 1,
                                        nullptr, 0, 0, nullptr, nullptr,
                                        nullptr, gtmph, 0, 0, M_T);
        // z[t+1] = cur + tc + relu((1-cos) * (cur @ Ws^T) + bs)
        gemm_fp16<<<gT, 256, GH_SMEM>>>(gsph, 1, 1, gcos, 2, W_l[L][1], bs, 1,
                                        gsp, 1, 1, nullptr, gtmph,
                                        gz, nullptr, 1, 1, M_T);
        copy_t0<<<(Bsz*NP*128 + 255)/256, 256>>>(gsp, gz);

        ln512<<<M_ALL/4, 512>>>(gz, lng, lnb, gtmph);
        gemm_fp16<<<gAll, 256, GH_SMEM>>>(gtmph, 0, 0, nullptr, 0, W_l[L][2], nullptr, 1,
                                          gx, 0, 0, nullptr, nullptr,
                                          gx, (L == 1) ? gxh : nullptr, 0, 0, M_ALL);
    }

    gemm_fp16<<<gAll, 256, GH_SMEM>>>(gxh, 0, 0, nullptr, 0, W_out, out_b, 0,
                                      nullptr, 0, 0, nullptr, nullptr,
                                      out, nullptr, 0, 0, M_ALL);
}